// round 6
// baseline (speedup 1.0000x reference)
#include <cuda_runtime.h>
#include <math.h>
#include <stdint.h>

#define B_ 4
#define T_ 2048
#define E_ 1024
#define H_ 16

// Device-global scratch (allocation-free).
// g_X:  tf32-rounded q,k,v inputs. g_Wp: rounded Wp. g_Wt: rounded W^T.
// g_Qf: Q A-fragment blobs  [b*16+h][qb(16)][ks(8)][rb(8)][lane(32)][4]
// g_Kf: K B-fragment blobs  [b*16+h][kt(32)][ks(8)][j(8)][lane(32)][2]
// g_Vf: V B-fragment blobs  (same shape as g_Kf)
// g_attn: flash output row-major [B,T,E]
__device__ float g_X[(size_t)3 * B_ * T_ * E_];
__device__ float g_Wp[(size_t)E_ * E_];
__device__ float g_Wt[(size_t)3 * E_ * E_];
__device__ float g_Qf[(size_t)64 * 16 * 8192];
__device__ float g_Kf[(size_t)64 * 32 * 4096];
__device__ float g_Vf[(size_t)64 * 32 * 4096];
__device__ float g_attn[(size_t)B_ * T_ * E_];

// ============================================================================
// Helpers
// ============================================================================
__device__ __forceinline__ uint32_t f2tf(float x) {
    uint32_t r;
    asm("cvt.rna.tf32.f32 %0, %1;" : "=r"(r) : "f"(x));
    return r;
}
__device__ __forceinline__ float rnd_tf(float x) { return __uint_as_float(f2tf(x)); }

__device__ __forceinline__ uint32_t smem_u32(const void* p) {
    uint32_t a;
    asm("{ .reg .u64 t; cvta.to.shared.u64 t, %1; cvt.u32.u64 %0, t; }"
        : "=r"(a) : "l"(p));
    return a;
}

__device__ __forceinline__ void mma8(float* c, const uint32_t* a, const uint32_t* b) {
    asm volatile(
        "mma.sync.aligned.m16n8k8.row.col.f32.tf32.tf32.f32 "
        "{%0,%1,%2,%3}, {%4,%5,%6,%7}, {%8,%9}, {%0,%1,%2,%3};"
        : "+f"(c[0]), "+f"(c[1]), "+f"(c[2]), "+f"(c[3])
        : "r"(a[0]), "r"(a[1]), "r"(a[2]), "r"(a[3]), "r"(b[0]), "r"(b[1]));
}

__device__ __forceinline__ void cp16(uint32_t dst, const void* src) {
    asm volatile("cp.async.cg.shared.global [%0], [%1], 16;"
                 :: "r"(dst), "l"(src));
}
#define CP_COMMIT asm volatile("cp.async.commit_group;" ::: "memory")
#define CP_WAIT0  asm volatile("cp.async.wait_group 0;" ::: "memory")
#define CP_WAIT1  asm volatile("cp.async.wait_group 1;" ::: "memory")

// ============================================================================
// Round pass: g_X[z] = rna_tf32(q|k|v), g_Wp = rna_tf32(Wp)
// ============================================================================
__global__ __launch_bounds__(256) void cvt_round_kernel(
    const float* __restrict__ q, const float* __restrict__ k,
    const float* __restrict__ v, const float* __restrict__ Wp)
{
    const int z = blockIdx.y;
    const float* src;
    float* dst;
    size_t n4;
    if (z < 3) {
        src = (z == 0 ? q : (z == 1 ? k : v));
        dst = g_X + (size_t)z * B_ * T_ * E_;
        n4  = (size_t)B_ * T_ * E_ / 4;
    } else {
        src = Wp;
        dst = g_Wp;
        n4  = (size_t)E_ * E_ / 4;
    }
    size_t i = (size_t)blockIdx.x * 256 + threadIdx.x;
    if (i < n4) {
        float4 x = ((const float4*)src)[i];
        float4 o;
        o.x = rnd_tf(x.x); o.y = rnd_tf(x.y);
        o.z = rnd_tf(x.z); o.w = rnd_tf(x.w);
        ((float4*)dst)[i] = o;
    }
}

// ============================================================================
// Weight transpose + round: g_Wt[which][h*64+d][e] = rna(W[which][h][e][d])
// ============================================================================
__global__ __launch_bounds__(256) void transpose_w_kernel(
    const float* __restrict__ Wq, const float* __restrict__ Wk,
    const float* __restrict__ Wv)
{
    __shared__ float tile[64][65];
    const int which = blockIdx.z;
    const int h     = blockIdx.y;
    const int e0    = blockIdx.x * 64;
    const float* W = (which == 0 ? Wq : (which == 1 ? Wk : Wv)) + (size_t)h * E_ * 64;
    const int tid = threadIdx.x;

#pragma unroll
    for (int u = 0; u < 16; u++) {
        int idx = tid + u * 256;
        int r = idx >> 6, c = idx & 63;
        tile[r][c] = W[(size_t)(e0 + r) * 64 + c];
    }
    __syncthreads();

    float* out = g_Wt + (size_t)which * E_ * E_;
#pragma unroll
    for (int u = 0; u < 16; u++) {
        int idx = tid + u * 256;
        int d = idx >> 6, ee = idx & 63;
        out[(size_t)(h * 64 + d) * E_ + e0 + ee] = rnd_tf(tile[ee][d]);
    }
}

// ============================================================================
// GEMM core (cp.async 3-stage): C[128,128] = A[128,K=1024] @ B[128,K=1024]^T
// 256 threads / 8 warps (4M x 2N), warp tile 32x64, BK=32, smem stride 36.
// ============================================================================
#define LDT 36
#define GS_STAGE (128 * LDT)
#define GEMM_SMEM_BYTES (6 * GS_STAGE * 4)

__device__ __forceinline__ void gemm_issue(
    const float* __restrict__ A, const float* __restrict__ Bm,
    uint32_t su, int c, int s, int tid)
{
    const float* Ac = A + (c << 5);
    const float* Bc = Bm + (c << 5);
    const uint32_t ab = su + (uint32_t)s * GS_STAGE * 4;
    const uint32_t bb = su + (uint32_t)(3 + s) * GS_STAGE * 4;
#pragma unroll
    for (int u = 0; u < 4; u++) {
        int idx = tid + (u << 8);
        int r = idx >> 3, qq = idx & 7;
        uint32_t so = (uint32_t)(r * LDT + (qq << 2)) * 4;
        cp16(ab + so, Ac + (size_t)r * E_ + (qq << 2));
        cp16(bb + so, Bc + (size_t)r * E_ + (qq << 2));
    }
    CP_COMMIT;
}

__device__ __forceinline__ void gemm_tile_async(
    const float* __restrict__ A, const float* __restrict__ Bm,
    uint32_t* smw, float C[2][8][4])
{
    const int tid = threadIdx.x, wid = tid >> 5, lane = tid & 31;
    const int g = lane >> 2, tg = lane & 3;
    const int mw = (wid & 3) * 32, nw = (wid >> 2) * 64;
    const uint32_t su = smem_u32(smw);

#pragma unroll
    for (int i = 0; i < 2; i++)
#pragma unroll
        for (int j = 0; j < 8; j++)
#pragma unroll
            for (int p = 0; p < 4; p++) C[i][j][p] = 0.f;

    gemm_issue(A, Bm, su, 0, 0, tid);
    gemm_issue(A, Bm, su, 1, 1, tid);

    int s = 0;
    for (int c = 0; c < 32; c++) {
        if (c < 31) { CP_WAIT1; } else { CP_WAIT0; }
        __syncthreads();
        if (c + 2 < 32) {
            int sn = s + 2; if (sn >= 3) sn -= 3;
            gemm_issue(A, Bm, su, c + 2, sn, tid);
        }
        const uint32_t* sA = smw + (size_t)s * GS_STAGE;
        const uint32_t* sB = smw + (size_t)(3 + s) * GS_STAGE;
#pragma unroll
        for (int ks = 0; ks < 4; ks++) {
            uint32_t af[2][4], bf[8][2];
#pragma unroll
            for (int i = 0; i < 2; i++) {
                int base = (mw + 16 * i + g) * LDT + tg + 8 * ks;
                af[i][0] = sA[base];
                af[i][1] = sA[base + 8 * LDT];
                af[i][2] = sA[base + 4];
                af[i][3] = sA[base + 8 * LDT + 4];
            }
#pragma unroll
            for (int j = 0; j < 8; j++) {
                int base = (nw + 8 * j + g) * LDT + tg + 8 * ks;
                bf[j][0] = sB[base];
                bf[j][1] = sB[base + 4];
            }
#pragma unroll
            for (int i = 0; i < 2; i++)
#pragma unroll
                for (int j = 0; j < 8; j++) mma8(C[i][j], af[i], bf[j]);
        }
        if (++s == 3) s = 0;
    }
}

// ============================================================================
// QKV projection: grid (T/128, E/128, 12 = which*4+b). xq scaled by 1/32.
// Epilogue scatters rounded values into fragment-blob layouts for flash.
// ============================================================================
__global__ __launch_bounds__(256, 2) void proj_mma_kernel()
{
    extern __shared__ uint32_t gsm[];
    const int which = blockIdx.z >> 2;
    const int b     = blockIdx.z & 3;
    const int t0    = blockIdx.x * 128;
    const int n0    = blockIdx.y * 128;
    const float* X  = g_X + ((size_t)which * B_ + b) * T_ * E_ + (size_t)t0 * E_;
    const float* Bm = g_Wt + (size_t)which * E_ * E_ + (size_t)n0 * E_;

    float C[2][8][4];
    gemm_tile_async(X, Bm, gsm, C);

    const float scale = (which == 0) ? 0.03125f : 1.0f;
    const int lane = threadIdx.x & 31, wid = threadIdx.x >> 5;
    const int ge = lane >> 2, te = lane & 3;
    const int mw = (wid & 3) * 32, nw = (wid >> 2) * 64;

#pragma unroll
    for (int i = 0; i < 2; i++) {
        int rbase = t0 + mw + 16 * i + ge;
#pragma unroll
        for (int j = 0; j < 8; j++) {
            int cbase = n0 + nw + 8 * j + 2 * te;
#pragma unroll
            for (int p = 0; p < 4; p++) {
                int t = rbase + 8 * (p >> 1);
                int cc = cbase + (p & 1);
                float val = rnd_tf(C[i][j][p] * scale);
                int h = cc >> 6, d = cc & 63;
                if (which == 0) {
                    int qb = t >> 7, tl = t & 127;
                    int rb = tl >> 4, g = tl & 7, hf = (tl >> 3) & 1;
                    int ks = d >> 3, tg = d & 3, pp = (d >> 2) & 1;
                    size_t addr = (((size_t)(b * 16 + h) * 16 + qb) * 8192) +
                                  (size_t)(((ks * 8 + rb) * 32 + 4 * g + tg) * 4 +
                                           2 * hf + pp);
                    g_Qf[addr] = val;
                } else if (which == 1) {
                    int kt = t >> 6, s = t & 63;
                    int jj = s >> 3, g = s & 7;
                    int ks = d >> 3, tg = d & 3, sl = (d >> 2) & 1;
                    size_t addr = (((size_t)(b * 16 + h) * 32 + kt) * 4096) +
                                  (size_t)(((ks * 8 + jj) * 32 + 4 * g + tg) * 2 + sl);
                    g_Kf[addr] = val;
                } else {
                    int kt = t >> 6, s = t & 63;
                    int tg = s & 3, ks = s >> 3, sl = (s >> 2) & 1;
                    int g = d & 7, jj = d >> 3;
                    size_t addr = (((size_t)(b * 16 + h) * 32 + kt) * 4096) +
                                  (size_t)(((ks * 8 + jj) * 32 + 4 * g + tg) * 2 + sl);
                    g_Vf[addr] = val;
                }
            }
        }
    }
}

// ============================================================================
// Output projection: out = g_attn @ g_Wp^T + bp (fp32 epilogue).
// ============================================================================
__global__ __launch_bounds__(256, 2) void outproj_mma_kernel(
    const float* __restrict__ bp, float* __restrict__ out)
{
    extern __shared__ uint32_t gsm[];
    const int m0 = blockIdx.x * 128;
    const int n0 = blockIdx.y * 128;

    float C[2][8][4];
    gemm_tile_async(g_attn + (size_t)m0 * E_, g_Wp + (size_t)n0 * E_, gsm, C);

    const int lane = threadIdx.x & 31, wid = threadIdx.x >> 5;
    const int g = lane >> 2, tg = lane & 3;
    const int mw = (wid & 3) * 32, nw = (wid >> 2) * 64;

#pragma unroll
    for (int i = 0; i < 2; i++) {
        size_t r = (size_t)(m0 + mw + 16 * i + g);
#pragma unroll
        for (int j = 0; j < 8; j++) {
            int cc = n0 + nw + 8 * j + 2 * tg;
            float2 bv = *(const float2*)&bp[cc];
            float2 v0 = {C[i][j][0] + bv.x, C[i][j][1] + bv.y};
            float2 v1 = {C[i][j][2] + bv.x, C[i][j][3] + bv.y};
            *(float2*)&out[r * E_ + cc] = v0;
            *(float2*)&out[(r + 8) * E_ + cc] = v1;
        }
    }
}

// ============================================================================
// Causal flash attention: 128-row CTA, 4 warps x 32 rows, fragment blobs.
// Q blob (32KB) loaded once; K double-buffered (16KB x2); V single (16KB).
// P transported via warp shuffles (no smem). grid (T/128, B*H), 128 threads.
// ============================================================================
#define FL_QW 8192
#define FL_KW 4096
#define FLASH_SMEM_BYTES ((FL_QW + 2 * FL_KW + FL_KW) * 4)   // 81920

__global__ __launch_bounds__(128, 2) void flash_mma_kernel()
{
    extern __shared__ uint32_t smf[];
    uint32_t* Qs  = smf;                       // Q frag blob
    uint32_t* Ks2 = smf + FL_QW;               // 2 K stages
    uint32_t* Vs  = smf + FL_QW + 2 * FL_KW;   // 1 V stage

    const int bh = blockIdx.y;
    const int b  = bh >> 4, h = bh & 15;
    const int qb = gridDim.x - 1 - blockIdx.x;   // longest CTAs first
    const int tid = threadIdx.x, w = tid >> 5, lane = tid & 31;
    const int g = lane >> 2, tg = lane & 3;
    const int last = 2 * qb + 1;

    const float* Qg = g_Qf + ((size_t)bh * 16 + qb) * FL_QW;
    const float* Kg = g_Kf + (size_t)bh * 32 * FL_KW;
    const float* Vg = g_Vf + (size_t)bh * 32 * FL_KW;

    const uint32_t qs_u = smem_u32(Qs);
    const uint32_t ks_u = smem_u32(Ks2);
    const uint32_t vs_u = smem_u32(Vs);

    // ---- prologue: Q (once), K0, V0, K1 in flight ----
    {
#pragma unroll
        for (int u = 0; u < 16; u++) {
            int idx = tid + (u << 7);
            cp16(qs_u + (uint32_t)idx * 16, Qg + (size_t)idx * 4);
        }
        CP_COMMIT;
#pragma unroll
        for (int u = 0; u < 8; u++) {
            int idx = tid + (u << 7);
            cp16(ks_u + (uint32_t)idx * 16, Kg + (size_t)idx * 4);
        }
        CP_COMMIT;
#pragma unroll
        for (int u = 0; u < 8; u++) {
            int idx = tid + (u << 7);
            cp16(vs_u + (uint32_t)idx * 16, Vg + (size_t)idx * 4);
        }
        CP_COMMIT;
#pragma unroll
        for (int u = 0; u < 8; u++) {
            int idx = tid + (u << 7);
            cp16(ks_u + (uint32_t)(FL_KW * 4) + (uint32_t)idx * 16,
                 Kg + (size_t)FL_KW + (size_t)idx * 4);
        }
        CP_COMMIT;
    }

    float O[2][8][4];
    float m_s[2][2], l_s[2][2];
#pragma unroll
    for (int i = 0; i < 2; i++) {
#pragma unroll
        for (int hf = 0; hf < 2; hf++) { m_s[i][hf] = -INFINITY; l_s[i][hf] = 0.f; }
#pragma unroll
        for (int j = 0; j < 8; j++)
#pragma unroll
            for (int p = 0; p < 4; p++) O[i][j][p] = 0.f;
    }

    const int wr = qb * 128 + 32 * w;   // warp's first global row
    const int srcA = 4 * g + (tg >> 1);
    const int srcB = srcA + 2;
    const bool bsel = (tg & 1) != 0;

    for (int kt = 0; kt <= last; kt++) {
        if (kt < last) { CP_WAIT1; } else { CP_WAIT0; }
        __syncthreads();

        const uint2* Kf = (const uint2*)(Ks2 + (size_t)(kt & 1) * FL_KW);
        const uint4* Qf4 = (const uint4*)Qs;

        // ---- S = Q @ K^T ----
        float S[2][8][4];
#pragma unroll
        for (int i = 0; i < 2; i++)
#pragma unroll
            for (int j = 0; j < 8; j++)
#pragma unroll
                for (int p = 0; p < 4; p++) S[i][j][p] = 0.f;

#pragma unroll
        for (int ks = 0; ks < 8; ks++) {
            uint32_t a0[4], a1[4];
            {
                uint4 qa = Qf4[(ks * 8 + 2 * w + 0) * 32 + lane];
                a0[0] = qa.x; a0[1] = qa.z; a0[2] = qa.y; a0[3] = qa.w;
                uint4 qb4 = Qf4[(ks * 8 + 2 * w + 1) * 32 + lane];
                a1[0] = qb4.x; a1[1] = qb4.z; a1[2] = qb4.y; a1[3] = qb4.w;
            }
#pragma unroll
            for (int j = 0; j < 8; j++) {
                uint2 bf = Kf[(ks * 8 + j) * 32 + lane];
                uint32_t bb[2] = {bf.x, bf.y};
                mma8(S[0][j], a0, bb);
                mma8(S[1][j], a1, bb);
            }
        }

        // ---- causal mask (only last two tiles can clip) ----
        if (kt >= 2 * qb) {
            const int kb = kt * 64;
#pragma unroll
            for (int i = 0; i < 2; i++) {
                int r0 = wr + 16 * i + g;
#pragma unroll
                for (int j = 0; j < 8; j++) {
                    int c0 = kb + 8 * j + 2 * tg;
                    if (c0 > r0)         S[i][j][0] = -INFINITY;
                    if (c0 + 1 > r0)     S[i][j][1] = -INFINITY;
                    if (c0 > r0 + 8)     S[i][j][2] = -INFINITY;
                    if (c0 + 1 > r0 + 8) S[i][j][3] = -INFINITY;
                }
            }
        }

        // ---- online softmax (4 row-slots per lane) ----
#pragma unroll
        for (int i = 0; i < 2; i++) {
            float rm0 = -INFINITY, rm1 = -INFINITY;
#pragma unroll
            for (int j = 0; j < 8; j++) {
                rm0 = fmaxf(rm0, fmaxf(S[i][j][0], S[i][j][1]));
                rm1 = fmaxf(rm1, fmaxf(S[i][j][2], S[i][j][3]));
            }
            rm0 = fmaxf(rm0, __shfl_xor_sync(0xffffffffu, rm0, 1));
            rm0 = fmaxf(rm0, __shfl_xor_sync(0xffffffffu, rm0, 2));
            rm1 = fmaxf(rm1, __shfl_xor_sync(0xffffffffu, rm1, 1));
            rm1 = fmaxf(rm1, __shfl_xor_sync(0xffffffffu, rm1, 2));

            float mn0 = fmaxf(m_s[i][0], rm0), mn1 = fmaxf(m_s[i][1], rm1);
            float a0 = __expf(m_s[i][0] - mn0), a1 = __expf(m_s[i][1] - mn1);
            float s0 = 0.f, s1 = 0.f;
#pragma unroll
            for (int j = 0; j < 8; j++) {
                S[i][j][0] = __expf(S[i][j][0] - mn0);
                S[i][j][1] = __expf(S[i][j][1] - mn0);
                S[i][j][2] = __expf(S[i][j][2] - mn1);
                S[i][j][3] = __expf(S[i][j][3] - mn1);
                s0 += S[i][j][0] + S[i][j][1];
                s1 += S[i][j][2] + S[i][j][3];
            }
            s0 += __shfl_xor_sync(0xffffffffu, s0, 1);
            s0 += __shfl_xor_sync(0xffffffffu, s0, 2);
            s1 += __shfl_xor_sync(0xffffffffu, s1, 1);
            s1 += __shfl_xor_sync(0xffffffffu, s1, 2);
            l_s[i][0] = l_s[i][0] * a0 + s0;
            l_s[i][1] = l_s[i][1] * a1 + s1;
            m_s[i][0] = mn0;
            m_s[i][1] = mn1;
#pragma unroll
            for (int j = 0; j < 8; j++) {
                O[i][j][0] *= a0; O[i][j][1] *= a0;
                O[i][j][2] *= a1; O[i][j][3] *= a1;
            }
        }

        // ---- round P to tf32 in-place ----
#pragma unroll
        for (int i = 0; i < 2; i++)
#pragma unroll
            for (int j = 0; j < 8; j++)
#pragma unroll
                for (int p = 0; p < 4; p++)
                    S[i][j][p] = __uint_as_float(f2tf(S[i][j][p]));

        // ---- O += P @ V  (A-frags via warp shuffles, B-frags from V blob) ----
        const uint2* Vf = (const uint2*)Vs;
#pragma unroll
        for (int ks = 0; ks < 8; ks++) {
            uint32_t ap[2][4];
#pragma unroll
            for (int i = 0; i < 2; i++) {
                float p0 = __shfl_sync(0xffffffffu, S[i][ks][0], srcA);
                float p1 = __shfl_sync(0xffffffffu, S[i][ks][1], srcA);
                float p2 = __shfl_sync(0xffffffffu, S[i][ks][2], srcA);
                float p3 = __shfl_sync(0xffffffffu, S[i][ks][3], srcA);
                float q0 = __shfl_sync(0xffffffffu, S[i][ks][0], srcB);
                float q1 = __shfl_sync(0xffffffffu, S[i][ks][1], srcB);
                float q2 = __shfl_sync(0xffffffffu, S[i][ks][2], srcB);
                float q3 = __shfl_sync(0xffffffffu, S[i][ks][3], srcB);
                ap[i][0] = __float_as_uint(bsel ? p1 : p0);
                ap[i][1] = __float_as_uint(bsel ? p3 : p2);
                ap[i][2] = __float_as_uint(bsel ? q1 : q0);
                ap[i][3] = __float_as_uint(bsel ? q3 : q2);
            }
#pragma unroll
            for (int j = 0; j < 8; j++) {
                uint2 bf = Vf[(ks * 8 + j) * 32 + lane];
                uint32_t bb[2] = {bf.x, bf.y};
                mma8(O[0][j], ap[0], bb);
                mma8(O[1][j], ap[1], bb);
            }
        }

        // ---- refill V (single buffer) + next K stage ----
        __syncthreads();   // all warps finished reading Vs / Ks(kt)
        if (kt + 1 <= last) {
#pragma unroll
            for (int u = 0; u < 8; u++) {
                int idx = tid + (u << 7);
                cp16(vs_u + (uint32_t)idx * 16,
                     Vg + (size_t)(kt + 1) * FL_KW + (size_t)idx * 4);
            }
            CP_COMMIT;
            if (kt + 2 <= last) {
#pragma unroll
                for (int u = 0; u < 8; u++) {
                    int idx = tid + (u << 7);
                    cp16(ks_u + (uint32_t)(((kt + 2) & 1) * FL_KW * 4) +
                             (uint32_t)idx * 16,
                         Kg + (size_t)(kt + 2) * FL_KW + (size_t)idx * 4);
                }
                CP_COMMIT;
            }
        }
    }

    // ---- epilogue: normalize, round to tf32, write row-major [B,T,E] ----
#pragma unroll
    for (int i = 0; i < 2; i++) {
        float inv0 = 1.f / l_s[i][0], inv1 = 1.f / l_s[i][1];
        float* outp = g_attn +
            ((size_t)b * T_ + (size_t)(wr + 16 * i + g)) * E_ + h * 64;
#pragma unroll
        for (int j = 0; j < 8; j++) {
            int cc = 8 * j + 2 * tg;
            float2 v0 = {rnd_tf(O[i][j][0] * inv0), rnd_tf(O[i][j][1] * inv0)};
            float2 v1 = {rnd_tf(O[i][j][2] * inv1), rnd_tf(O[i][j][3] * inv1)};
            *(float2*)&outp[cc] = v0;
            *(float2*)(outp + 8 * E_ + cc) = v1;
        }
    }
}

// ============================================================================
extern "C" void kernel_launch(void* const* d_in, const int* in_sizes, int n_in,
                              void* d_out, int out_size)
{
    // metadata order: k, q, v, mask, Wk, Wq, Wv, Wp, bp
    const float* k  = (const float*)d_in[0];
    const float* q  = (const float*)d_in[1];
    const float* v  = (const float*)d_in[2];
    const float* Wk = (const float*)d_in[4];
    const float* Wq = (const float*)d_in[5];
    const float* Wv = (const float*)d_in[6];
    const float* Wp = (const float*)d_in[7];
    const float* bp = (const float*)d_in[8];
    float* out = (float*)d_out;

    cudaFuncSetAttribute(proj_mma_kernel,
                         cudaFuncAttributeMaxDynamicSharedMemorySize, GEMM_SMEM_BYTES);
    cudaFuncSetAttribute(outproj_mma_kernel,
                         cudaFuncAttributeMaxDynamicSharedMemorySize, GEMM_SMEM_BYTES);
    cudaFuncSetAttribute(flash_mma_kernel,
                         cudaFuncAttributeMaxDynamicSharedMemorySize, FLASH_SMEM_BYTES);

    cvt_round_kernel<<<dim3(8192, 4), 256>>>(q, k, v, Wp);

    transpose_w_kernel<<<dim3(E_ / 64, H_, 3), 256>>>(Wq, Wk, Wv);

    proj_mma_kernel<<<dim3(T_ / 128, E_ / 128, 12), 256, GEMM_SMEM_BYTES>>>();

    flash_mma_kernel<<<dim3(T_ / 128, B_ * H_), 128, FLASH_SMEM_BYTES>>>();

    outproj_mma_kernel<<<dim3((B_ * T_) / 128, E_ / 128), 256, GEMM_SMEM_BYTES>>>(bp, out);
}

// round 7
// speedup vs baseline: 1.8076x; 1.8076x over previous
#include <cuda_runtime.h>
#include <cuda_fp16.h>
#include <math.h>
#include <stdint.h>

#define B_ 4
#define T_ 2048
#define E_ 1024
#define H_ 16

// Device-global scratch (allocation-free).
// g_Xh:  fp16 copies of q,k,v. g_Wph: fp16 Wp. g_Wth: fp16 W^T (row n=h*64+d).
// g_Qfh: Q A-frag blobs  [bh][qb(16)][ks(4)][rb(8)][lane(32)][4 regs]  (uint32=fp16x2)
// g_Kfh: K B-frag blobs  [bh][kt(32)][ks(4)][j(8)][lane(32)][2 regs]
// g_Vfh: V B-frag blobs  (same shape as K)
// g_attnh: flash output fp16 row-major [B,T,E]
__device__ __half   g_Xh[(size_t)3 * B_ * T_ * E_];
__device__ __half   g_Wph[(size_t)E_ * E_];
__device__ __half   g_Wth[(size_t)3 * E_ * E_];
__device__ uint32_t g_Qfh[(size_t)64 * 16 * 4096];
__device__ uint32_t g_Kfh[(size_t)64 * 32 * 2048];
__device__ uint32_t g_Vfh[(size_t)64 * 32 * 2048];
__device__ __half   g_attnh[(size_t)B_ * T_ * E_];

// ============================================================================
// Helpers
// ============================================================================
__device__ __forceinline__ uint32_t packh2(float lo, float hi) {
    uint32_t r;
    asm("cvt.rn.f16x2.f32 %0, %1, %2;" : "=r"(r) : "f"(hi), "f"(lo));
    return r;
}

__device__ __forceinline__ uint32_t smem_u32(const void* p) {
    uint32_t a;
    asm("{ .reg .u64 t; cvta.to.shared.u64 t, %1; cvt.u32.u64 %0, t; }"
        : "=r"(a) : "l"(p));
    return a;
}

// D(16x8,f32) += A(16x16,f16) * B(16x8,f16)
__device__ __forceinline__ void mma16h(float* c, const uint32_t* a, const uint32_t* b) {
    asm volatile(
        "mma.sync.aligned.m16n8k16.row.col.f32.f16.f16.f32 "
        "{%0,%1,%2,%3}, {%4,%5,%6,%7}, {%8,%9}, {%0,%1,%2,%3};"
        : "+f"(c[0]), "+f"(c[1]), "+f"(c[2]), "+f"(c[3])
        : "r"(a[0]), "r"(a[1]), "r"(a[2]), "r"(a[3]), "r"(b[0]), "r"(b[1]));
}

__device__ __forceinline__ void cp16(uint32_t dst, const void* src) {
    asm volatile("cp.async.cg.shared.global [%0], [%1], 16;"
                 :: "r"(dst), "l"(src));
}
#define CP_COMMIT asm volatile("cp.async.commit_group;" ::: "memory")
#define CP_WAIT0  asm volatile("cp.async.wait_group 0;" ::: "memory")
#define CP_WAIT1  asm volatile("cp.async.wait_group 1;" ::: "memory")

// ============================================================================
// Convert pass: g_Xh[z] = fp16(q|k|v), g_Wph = fp16(Wp)
// ============================================================================
__global__ __launch_bounds__(256) void cvt_h_kernel(
    const float* __restrict__ q, const float* __restrict__ k,
    const float* __restrict__ v, const float* __restrict__ Wp)
{
    const int z = blockIdx.y;
    const float* src;
    __half* dst;
    size_t n4;
    if (z < 3) {
        src = (z == 0 ? q : (z == 1 ? k : v));
        dst = g_Xh + (size_t)z * B_ * T_ * E_;
        n4  = (size_t)B_ * T_ * E_ / 4;
    } else {
        src = Wp;
        dst = g_Wph;
        n4  = (size_t)E_ * E_ / 4;
    }
    size_t i = (size_t)blockIdx.x * 256 + threadIdx.x;
    if (i < n4) {
        float4 x = ((const float4*)src)[i];
        uint2 o;
        o.x = packh2(x.x, x.y);
        o.y = packh2(x.z, x.w);
        ((uint2*)dst)[i] = o;
    }
}

// ============================================================================
// Weight transpose: g_Wth[which][h*64+d][e] = fp16(W[which][h][e][d])
// ============================================================================
__global__ __launch_bounds__(256) void transpose_w_kernel(
    const float* __restrict__ Wq, const float* __restrict__ Wk,
    const float* __restrict__ Wv)
{
    __shared__ float tile[64][65];
    const int which = blockIdx.z;
    const int h     = blockIdx.y;
    const int e0    = blockIdx.x * 64;
    const float* W = (which == 0 ? Wq : (which == 1 ? Wk : Wv)) + (size_t)h * E_ * 64;
    const int tid = threadIdx.x;

#pragma unroll
    for (int u = 0; u < 16; u++) {
        int idx = tid + u * 256;
        int r = idx >> 6, c = idx & 63;
        tile[r][c] = W[(size_t)(e0 + r) * 64 + c];
    }
    __syncthreads();

    __half* out = g_Wth + (size_t)which * E_ * E_;
#pragma unroll
    for (int u = 0; u < 16; u++) {
        int idx = tid + u * 256;
        int d = idx >> 6, ee = idx & 63;
        out[(size_t)(h * 64 + d) * E_ + e0 + ee] = __float2half_rn(tile[ee][d]);
    }
}

// ============================================================================
// fp16 GEMM core (cp.async 3-stage): C[128,128] = A[128,K] @ B[128,K]^T
// K=1024, BK=32 (2 k16 steps/chunk). 256 threads / 8 warps (4M x 2N),
// warp tile 32x64. smem row = 40 halves (20 words) — conflict-free frag LDS.
// ============================================================================
#define HLD 20                               // uint32 words per smem row
#define GSW (128 * HLD)                      // words per operand stage
#define GEMM_SMEM_BYTES (6 * GSW * 4)        // 61440

__device__ __forceinline__ void gemm_issue_h(
    const __half* __restrict__ A, const __half* __restrict__ Bm,
    uint32_t su, int c, int s, int tid)
{
    const __half* Ac = A + (c << 5);
    const __half* Bc = Bm + (c << 5);
    const uint32_t ab = su + (uint32_t)s * GSW * 4;
    const uint32_t bb = su + (uint32_t)(3 + s) * GSW * 4;
#pragma unroll
    for (int u = 0; u < 2; u++) {
        int idx = tid + (u << 8);           // 0..511
        int r = idx >> 2, qq = idx & 3;
        uint32_t so = (uint32_t)r * 80 + (uint32_t)qq * 16;
        cp16(ab + so, Ac + (size_t)r * E_ + (qq << 3));
        cp16(bb + so, Bc + (size_t)r * E_ + (qq << 3));
    }
    CP_COMMIT;
}

__device__ __forceinline__ void gemm_tile_h(
    const __half* __restrict__ A, const __half* __restrict__ Bm,
    uint32_t* smw, float C[2][8][4])
{
    const int tid = threadIdx.x, wid = tid >> 5, lane = tid & 31;
    const int g = lane >> 2, tg = lane & 3;
    const int mw = (wid & 3) * 32, nw = (wid >> 2) * 64;
    const uint32_t su = smem_u32(smw);

#pragma unroll
    for (int i = 0; i < 2; i++)
#pragma unroll
        for (int j = 0; j < 8; j++)
#pragma unroll
            for (int p = 0; p < 4; p++) C[i][j][p] = 0.f;

    gemm_issue_h(A, Bm, su, 0, 0, tid);
    gemm_issue_h(A, Bm, su, 1, 1, tid);

    int s = 0;
    for (int c = 0; c < 32; c++) {
        if (c < 31) { CP_WAIT1; } else { CP_WAIT0; }
        __syncthreads();
        if (c + 2 < 32) {
            int sn = s + 2; if (sn >= 3) sn -= 3;
            gemm_issue_h(A, Bm, su, c + 2, sn, tid);
        }
        const uint32_t* sA = smw + (size_t)s * GSW;
        const uint32_t* sB = smw + (size_t)(3 + s) * GSW;
#pragma unroll
        for (int ks = 0; ks < 2; ks++) {
            const int ko = ks * 8;
            uint32_t af[2][4], bf[8][2];
#pragma unroll
            for (int i = 0; i < 2; i++) {
                int base = (mw + 16 * i + g) * HLD + ko + tg;
                af[i][0] = sA[base];
                af[i][1] = sA[base + 8 * HLD];
                af[i][2] = sA[base + 4];
                af[i][3] = sA[base + 8 * HLD + 4];
            }
#pragma unroll
            for (int j = 0; j < 8; j++) {
                int base = (nw + 8 * j + g) * HLD + ko + tg;
                bf[j][0] = sB[base];
                bf[j][1] = sB[base + 4];
            }
#pragma unroll
            for (int i = 0; i < 2; i++)
#pragma unroll
                for (int j = 0; j < 8; j++) mma16h(C[i][j], af[i], bf[j]);
        }
        if (++s == 3) s = 0;
    }
}

// ============================================================================
// QKV projection: grid (T/128, E/128, 12 = which*4+b).
// Epilogue packs fp16x2 and scatters into fragment blobs. Q stays UNscaled
// (1/32 applied to S in flash, fp32).
// ============================================================================
__global__ __launch_bounds__(256, 2) void proj_mma_kernel()
{
    extern __shared__ uint32_t gsm[];
    const int which = blockIdx.z >> 2;
    const int b     = blockIdx.z & 3;
    const int t0    = blockIdx.x * 128;
    const int n0    = blockIdx.y * 128;
    const __half* X  = g_Xh + ((size_t)which * B_ + b) * T_ * E_ + (size_t)t0 * E_;
    const __half* Bm = g_Wth + (size_t)which * E_ * E_ + (size_t)n0 * E_;

    float C[2][8][4];
    gemm_tile_h(X, Bm, gsm, C);

    const int lane = threadIdx.x & 31, wid = threadIdx.x >> 5;
    const int ge = lane >> 2, te = lane & 3;
    const int mw = (wid & 3) * 32, nw = (wid >> 2) * 64;

#pragma unroll
    for (int i = 0; i < 2; i++) {
        const int t_lo = t0 + mw + 16 * i + ge;    // rows: p01 at t_lo, p23 at t_lo+8
#pragma unroll
        for (int j = 0; j < 8; j++) {
            const int c  = n0 + nw + 8 * j + 2 * te;   // even d-pair base
            const int h  = c >> 6, d = c & 63;
            const int bh = b * 16 + h;

            if (which == 0) {
                uint32_t w01 = packh2(C[i][j][0], C[i][j][1]);
                uint32_t w23 = packh2(C[i][j][2], C[i][j][3]);
                int qb = t_lo >> 7, tl = t_lo & 127;
                int rb = tl >> 4, gp = tl & 7;
                int ks = d >> 4, dk = d & 15;
                int tgp = (dk >> 1) & 3, rhi = (dk >> 3) << 1;
                size_t idx = ((size_t)bh * 16 + qb) * 4096 +
                             (size_t)(((ks * 8 + rb) * 32 + 4 * gp + tgp) * 4 + rhi);
                uint2 st; st.x = w01; st.y = w23;        // regs rhi, rhi+1
                *(uint2*)&g_Qfh[idx] = st;
            } else if (which == 1) {
                uint32_t w01 = packh2(C[i][j][0], C[i][j][1]);
                uint32_t w23 = packh2(C[i][j][2], C[i][j][3]);
                int kt = t_lo >> 6, sidx = t_lo & 63;
                int jp = sidx >> 3, gp = sidx & 7;       // gp = ge (<8)
                int ks = d >> 4, dk = d & 15;
                int reg = dk >> 3, tgp = (dk >> 1) & 3;
                size_t base = ((size_t)bh * 32 + kt) * 2048;
                g_Kfh[base + ((ks * 8 + jp) * 32 + 4 * gp + tgp) * 2 + reg] = w01;
                g_Kfh[base + ((ks * 8 + jp + 1) * 32 + 4 * gp + tgp) * 2 + reg] = w23;
            } else {
                // V: pairs along the row (s) dim — swap across lane^4 (ge^1)
                float q0 = __shfl_xor_sync(0xffffffffu, C[i][j][0], 4);
                float q1 = __shfl_xor_sync(0xffffffffu, C[i][j][1], 4);
                float q2 = __shfl_xor_sync(0xffffffffu, C[i][j][2], 4);
                float q3 = __shfl_xor_sync(0xffffffffu, C[i][j][3], 4);
                if ((ge & 1) == 0) {
                    uint32_t wA = packh2(C[i][j][0], q0);   // (s, d),(s+1, d)
                    uint32_t wB = packh2(C[i][j][1], q1);   // (s, d+1)
                    uint32_t wC = packh2(C[i][j][2], q2);   // (s+8, d)
                    uint32_t wD = packh2(C[i][j][3], q3);   // (s+8, d+1)
                    int kt = t_lo >> 6, sidx = t_lo & 63;   // even
                    int ks = sidx >> 4, sk = sidx & 15;     // sk = ge < 8 -> reg0
                    int tgp = (sk >> 1) & 3;
                    int jp = d >> 3, gp = d & 7;            // gp even
                    size_t base = ((size_t)bh * 32 + kt) * 2048;
                    size_t iA = base + ((ks * 8 + jp) * 32 + 4 * gp + tgp) * 2;
                    size_t iB = base + ((ks * 8 + jp) * 32 + 4 * (gp + 1) + tgp) * 2;
                    uint2 s0; s0.x = wA; s0.y = wC;          // regs 0,1 (s and s+8)
                    uint2 s1; s1.x = wB; s1.y = wD;
                    *(uint2*)&g_Vfh[iA] = s0;
                    *(uint2*)&g_Vfh[iB] = s1;
                }
            }
        }
    }
}

// ============================================================================
// Output projection: out = attn(fp16) @ Wp(fp16)^T + bp (fp32 epilogue).
// ============================================================================
__global__ __launch_bounds__(256, 2) void outproj_mma_kernel(
    const float* __restrict__ bp, float* __restrict__ out)
{
    extern __shared__ uint32_t gsm[];
    const int m0 = blockIdx.x * 128;
    const int n0 = blockIdx.y * 128;

    float C[2][8][4];
    gemm_tile_h(g_attnh + (size_t)m0 * E_, g_Wph + (size_t)n0 * E_, gsm, C);

    const int lane = threadIdx.x & 31, wid = threadIdx.x >> 5;
    const int g = lane >> 2, tg = lane & 3;
    const int mw = (wid & 3) * 32, nw = (wid >> 2) * 64;

#pragma unroll
    for (int i = 0; i < 2; i++) {
        size_t r = (size_t)(m0 + mw + 16 * i + g);
#pragma unroll
        for (int j = 0; j < 8; j++) {
            int cc = n0 + nw + 8 * j + 2 * tg;
            float2 bv = *(const float2*)&bp[cc];
            float2 v0 = {C[i][j][0] + bv.x, C[i][j][1] + bv.y};
            float2 v1 = {C[i][j][2] + bv.x, C[i][j][3] + bv.y};
            *(float2*)&out[r * E_ + cc] = v0;
            *(float2*)&out[(r + 8) * E_ + cc] = v1;
        }
    }
}

// ============================================================================
// Causal flash attention, fp16 m16n8k16. 128-row CTA, 4 warps x 32 rows.
// Q blob once (16KB); K,V double-buffered (8KB each stage). P via register
// fp16x2 packs (FA2 trick) — zero smem / shuffles in the hot loop.
// grid (T/128, B*H), 128 threads. S scaled by 1/32 in fp32 post-MMA.
// ============================================================================
#define FQW 4096
#define FKW 2048
#define FLASH_SMEM_BYTES ((FQW + 2 * FKW + 2 * FKW) * 4)   // 49152

__global__ __launch_bounds__(128, 2) void flash_mma_kernel()
{
    extern __shared__ uint32_t smf[];
    uint32_t* Qs  = smf;                    // Q frag blob
    uint32_t* Ks2 = smf + FQW;              // 2 K stages
    uint32_t* Vs2 = smf + FQW + 2 * FKW;    // 2 V stages

    const int bh = blockIdx.y;
    const int b  = bh >> 4, h = bh & 15;
    const int qb = gridDim.x - 1 - blockIdx.x;   // longest CTAs first
    const int tid = threadIdx.x, w = tid >> 5, lane = tid & 31;
    const int g = lane >> 2, tg = lane & 3;
    const int last = 2 * qb + 1;

    const uint32_t* Qg = g_Qfh + ((size_t)bh * 16 + qb) * FQW;
    const uint32_t* Kg = g_Kfh + (size_t)bh * 32 * FKW;
    const uint32_t* Vg = g_Vfh + (size_t)bh * 32 * FKW;

    const uint32_t qs_u = smem_u32(Qs);
    const uint32_t ks_u = smem_u32(Ks2);
    const uint32_t vs_u = smem_u32(Vs2);

    auto issueKV = [&](int kt) {
        const uint32_t kb = ks_u + (uint32_t)((kt & 1) * FKW * 4);
        const uint32_t vb = vs_u + (uint32_t)((kt & 1) * FKW * 4);
        const uint32_t* Kp = Kg + (size_t)kt * FKW;
        const uint32_t* Vp = Vg + (size_t)kt * FKW;
#pragma unroll
        for (int u = 0; u < 4; u++) {
            int idx = tid + (u << 7);       // 0..511 chunks
            cp16(kb + (uint32_t)idx * 16, Kp + (size_t)idx * 4);
            cp16(vb + (uint32_t)idx * 16, Vp + (size_t)idx * 4);
        }
        CP_COMMIT;
    };

    // prologue: Q + KV0 (group 1), KV1 (group 2)
    {
#pragma unroll
        for (int u = 0; u < 8; u++) {
            int idx = tid + (u << 7);       // 0..1023 chunks
            cp16(qs_u + (uint32_t)idx * 16, Qg + (size_t)idx * 4);
        }
#pragma unroll
        for (int u = 0; u < 4; u++) {
            int idx = tid + (u << 7);
            cp16(ks_u + (uint32_t)idx * 16, Kg + (size_t)idx * 4);
            cp16(vs_u + (uint32_t)idx * 16, Vg + (size_t)idx * 4);
        }
        CP_COMMIT;
        if (last >= 1) issueKV(1);
    }

    uint32_t qf[2][4][4];
    float O[2][8][4];
    float m_s[2][2], l_s[2][2];
#pragma unroll
    for (int i = 0; i < 2; i++) {
#pragma unroll
        for (int hf = 0; hf < 2; hf++) { m_s[i][hf] = -INFINITY; l_s[i][hf] = 0.f; }
#pragma unroll
        for (int j = 0; j < 8; j++)
#pragma unroll
            for (int p = 0; p < 4; p++) O[i][j][p] = 0.f;
    }

    const int wr = qb * 128 + 32 * w;   // warp's first global row

    for (int kt = 0; kt <= last; kt++) {
        if (kt < last) { CP_WAIT1; } else { CP_WAIT0; }
        __syncthreads();

        if (kt == 0) {
            const uint4* Qf4 = (const uint4*)Qs;
#pragma unroll
            for (int ks = 0; ks < 4; ks++)
#pragma unroll
                for (int i = 0; i < 2; i++) {
                    uint4 qa = Qf4[(ks * 8 + 2 * w + i) * 32 + lane];
                    qf[i][ks][0] = qa.x; qf[i][ks][1] = qa.y;
                    qf[i][ks][2] = qa.z; qf[i][ks][3] = qa.w;
                }
        }

        const uint2* Kf = (const uint2*)(Ks2 + (size_t)(kt & 1) * FKW);
        const uint2* Vf = (const uint2*)(Vs2 + (size_t)(kt & 1) * FKW);

        // ---- S = Q @ K^T ----
        float S[2][8][4];
#pragma unroll
        for (int i = 0; i < 2; i++)
#pragma unroll
            for (int j = 0; j < 8; j++)
#pragma unroll
                for (int p = 0; p < 4; p++) S[i][j][p] = 0.f;

#pragma unroll
        for (int ks = 0; ks < 4; ks++)
#pragma unroll
            for (int j = 0; j < 8; j++) {
                uint2 kb = Kf[(ks * 8 + j) * 32 + lane];
                uint32_t bb[2] = {kb.x, kb.y};
                mma16h(S[0][j], qf[0][ks], bb);
                mma16h(S[1][j], qf[1][ks], bb);
            }

        // ---- scale by 1/sqrt(E) in fp32 ----
#pragma unroll
        for (int i = 0; i < 2; i++)
#pragma unroll
            for (int j = 0; j < 8; j++)
#pragma unroll
                for (int p = 0; p < 4; p++) S[i][j][p] *= 0.03125f;

        // ---- causal mask (last two tiles only) ----
        if (kt >= 2 * qb) {
            const int kb0 = kt * 64;
#pragma unroll
            for (int i = 0; i < 2; i++) {
                int r0 = wr + 16 * i + g;
#pragma unroll
                for (int j = 0; j < 8; j++) {
                    int c0 = kb0 + 8 * j + 2 * tg;
                    if (c0 > r0)         S[i][j][0] = -INFINITY;
                    if (c0 + 1 > r0)     S[i][j][1] = -INFINITY;
                    if (c0 > r0 + 8)     S[i][j][2] = -INFINITY;
                    if (c0 + 1 > r0 + 8) S[i][j][3] = -INFINITY;
                }
            }
        }

        // ---- online softmax ----
#pragma unroll
        for (int i = 0; i < 2; i++) {
            float rm0 = -INFINITY, rm1 = -INFINITY;
#pragma unroll
            for (int j = 0; j < 8; j++) {
                rm0 = fmaxf(rm0, fmaxf(S[i][j][0], S[i][j][1]));
                rm1 = fmaxf(rm1, fmaxf(S[i][j][2], S[i][j][3]));
            }
            rm0 = fmaxf(rm0, __shfl_xor_sync(0xffffffffu, rm0, 1));
            rm0 = fmaxf(rm0, __shfl_xor_sync(0xffffffffu, rm0, 2));
            rm1 = fmaxf(rm1, __shfl_xor_sync(0xffffffffu, rm1, 1));
            rm1 = fmaxf(rm1, __shfl_xor_sync(0xffffffffu, rm1, 2));

            float mn0 = fmaxf(m_s[i][0], rm0), mn1 = fmaxf(m_s[i][1], rm1);
            float a0 = __expf(m_s[i][0] - mn0), a1 = __expf(m_s[i][1] - mn1);
            float s0 = 0.f, s1 = 0.f;
#pragma unroll
            for (int j = 0; j < 8; j++) {
                S[i][j][0] = __expf(S[i][j][0] - mn0);
                S[i][j][1] = __expf(S[i][j][1] - mn0);
                S[i][j][2] = __expf(S[i][j][2] - mn1);
                S[i][j][3] = __expf(S[i][j][3] - mn1);
                s0 += S[i][j][0] + S[i][j][1];
                s1 += S[i][j][2] + S[i][j][3];
            }
            s0 += __shfl_xor_sync(0xffffffffu, s0, 1);
            s0 += __shfl_xor_sync(0xffffffffu, s0, 2);
            s1 += __shfl_xor_sync(0xffffffffu, s1, 1);
            s1 += __shfl_xor_sync(0xffffffffu, s1, 2);
            l_s[i][0] = l_s[i][0] * a0 + s0;
            l_s[i][1] = l_s[i][1] * a1 + s1;
            m_s[i][0] = mn0;
            m_s[i][1] = mn1;
#pragma unroll
            for (int j = 0; j < 8; j++) {
                O[i][j][0] *= a0; O[i][j][1] *= a0;
                O[i][j][2] *= a1; O[i][j][3] *= a1;
            }
        }

        // ---- O += P @ V : P = C-frag packed to fp16x2 A-frags (FA2 trick) ----
#pragma unroll
        for (int ks = 0; ks < 4; ks++) {
            uint32_t ap[2][4];
#pragma unroll
            for (int i = 0; i < 2; i++) {
                ap[i][0] = packh2(S[i][2 * ks][0],     S[i][2 * ks][1]);
                ap[i][1] = packh2(S[i][2 * ks][2],     S[i][2 * ks][3]);
                ap[i][2] = packh2(S[i][2 * ks + 1][0], S[i][2 * ks + 1][1]);
                ap[i][3] = packh2(S[i][2 * ks + 1][2], S[i][2 * ks + 1][3]);
            }
#pragma unroll
            for (int j = 0; j < 8; j++) {
                uint2 vb = Vf[(ks * 8 + j) * 32 + lane];
                uint32_t bb[2] = {vb.x, vb.y};
                mma16h(O[0][j], ap[0], bb);
                mma16h(O[1][j], ap[1], bb);
            }
        }

        // ---- issue KV(kt+2) into the buffer just consumed ----
        __syncthreads();
        if (kt + 2 <= last) issueKV(kt + 2);
    }

    // ---- epilogue: normalize, pack fp16, write row-major [B,T,E] ----
#pragma unroll
    for (int i = 0; i < 2; i++) {
        float inv0 = 1.f / l_s[i][0], inv1 = 1.f / l_s[i][1];
        int row = wr + 16 * i + g;
        uint32_t* o0 = (uint32_t*)g_attnh + ((size_t)b * T_ + row) * (E_ / 2) + h * 32;
        uint32_t* o1 = o0 + 8 * (E_ / 2);
#pragma unroll
        for (int j = 0; j < 8; j++) {
            o0[4 * j + tg] = packh2(O[i][j][0] * inv0, O[i][j][1] * inv0);
            o1[4 * j + tg] = packh2(O[i][j][2] * inv1, O[i][j][3] * inv1);
        }
    }
}

// ============================================================================
extern "C" void kernel_launch(void* const* d_in, const int* in_sizes, int n_in,
                              void* d_out, int out_size)
{
    // metadata order: k, q, v, mask, Wk, Wq, Wv, Wp, bp
    const float* k  = (const float*)d_in[0];
    const float* q  = (const float*)d_in[1];
    const float* v  = (const float*)d_in[2];
    const float* Wk = (const float*)d_in[4];
    const float* Wq = (const float*)d_in[5];
    const float* Wv = (const float*)d_in[6];
    const float* Wp = (const float*)d_in[7];
    const float* bp = (const float*)d_in[8];
    float* out = (float*)d_out;

    cudaFuncSetAttribute(proj_mma_kernel,
                         cudaFuncAttributeMaxDynamicSharedMemorySize, GEMM_SMEM_BYTES);
    cudaFuncSetAttribute(outproj_mma_kernel,
                         cudaFuncAttributeMaxDynamicSharedMemorySize, GEMM_SMEM_BYTES);
    cudaFuncSetAttribute(flash_mma_kernel,
                         cudaFuncAttributeMaxDynamicSharedMemorySize, FLASH_SMEM_BYTES);

    cvt_h_kernel<<<dim3(8192, 4), 256>>>(q, k, v, Wp);

    transpose_w_kernel<<<dim3(E_ / 64, H_, 3), 256>>>(Wq, Wk, Wv);

    proj_mma_kernel<<<dim3(T_ / 128, E_ / 128, 12), 256, GEMM_SMEM_BYTES>>>();

    flash_mma_kernel<<<dim3(T_ / 128, B_ * H_), 128, FLASH_SMEM_BYTES>>>();

    outproj_mma_kernel<<<dim3((B_ * T_) / 128, E_ / 128), 256, GEMM_SMEM_BYTES>>>(bp, out);
}

// round 8
// speedup vs baseline: 1.9502x; 1.0789x over previous
#include <cuda_runtime.h>
#include <cuda_fp16.h>
#include <math.h>
#include <stdint.h>

#define B_ 4
#define T_ 2048
#define E_ 1024
#define H_ 16

// Device-global scratch (allocation-free).
__device__ __half   g_Xh[(size_t)3 * B_ * T_ * E_];
__device__ __half   g_Wph[(size_t)E_ * E_];
__device__ __half   g_Wth[(size_t)3 * E_ * E_];
__device__ uint32_t g_Qfh[(size_t)64 * 16 * 4096];
__device__ uint32_t g_Kfh[(size_t)64 * 32 * 2048];
__device__ uint32_t g_Vfh[(size_t)64 * 32 * 2048];
__device__ __half   g_attnh[(size_t)B_ * T_ * E_];

// ============================================================================
// Helpers
// ============================================================================
__device__ __forceinline__ uint32_t packh2(float lo, float hi) {
    uint32_t r;
    asm("cvt.rn.f16x2.f32 %0, %1, %2;" : "=r"(r) : "f"(hi), "f"(lo));
    return r;
}

__device__ __forceinline__ float ex2f(float x) {
    float y;
    asm("ex2.approx.f32 %0, %1;" : "=f"(y) : "f"(x));
    return y;
}

__device__ __forceinline__ uint32_t smem_u32(const void* p) {
    uint32_t a;
    asm("{ .reg .u64 t; cvta.to.shared.u64 t, %1; cvt.u32.u64 %0, t; }"
        : "=r"(a) : "l"(p));
    return a;
}

// D(16x8,f32) += A(16x16,f16) * B(16x8,f16)
__device__ __forceinline__ void mma16h(float* c, const uint32_t* a, const uint32_t* b) {
    asm volatile(
        "mma.sync.aligned.m16n8k16.row.col.f32.f16.f16.f32 "
        "{%0,%1,%2,%3}, {%4,%5,%6,%7}, {%8,%9}, {%0,%1,%2,%3};"
        : "+f"(c[0]), "+f"(c[1]), "+f"(c[2]), "+f"(c[3])
        : "r"(a[0]), "r"(a[1]), "r"(a[2]), "r"(a[3]), "r"(b[0]), "r"(b[1]));
}

__device__ __forceinline__ void ldsm4(uint32_t* r, uint32_t a) {
    asm volatile("ldmatrix.sync.aligned.m8n8.x4.shared.b16 {%0,%1,%2,%3}, [%4];"
                 : "=r"(r[0]), "=r"(r[1]), "=r"(r[2]), "=r"(r[3]) : "r"(a));
}

__device__ __forceinline__ void cp16(uint32_t dst, const void* src) {
    asm volatile("cp.async.cg.shared.global [%0], [%1], 16;"
                 :: "r"(dst), "l"(src));
}
#define CP_COMMIT asm volatile("cp.async.commit_group;" ::: "memory")
#define CP_WAIT0  asm volatile("cp.async.wait_group 0;" ::: "memory")
#define CP_WAIT1  asm volatile("cp.async.wait_group 1;" ::: "memory")

// ============================================================================
// Convert pass: g_Xh[z] = fp16(q|k|v), g_Wph = fp16(Wp)
// ============================================================================
__global__ __launch_bounds__(256) void cvt_h_kernel(
    const float* __restrict__ q, const float* __restrict__ k,
    const float* __restrict__ v, const float* __restrict__ Wp)
{
    const int z = blockIdx.y;
    const float* src;
    __half* dst;
    size_t n4;
    if (z < 3) {
        src = (z == 0 ? q : (z == 1 ? k : v));
        dst = g_Xh + (size_t)z * B_ * T_ * E_;
        n4  = (size_t)B_ * T_ * E_ / 4;
    } else {
        src = Wp;
        dst = g_Wph;
        n4  = (size_t)E_ * E_ / 4;
    }
    size_t i = (size_t)blockIdx.x * 256 + threadIdx.x;
    if (i < n4) {
        float4 x = ((const float4*)src)[i];
        uint2 o;
        o.x = packh2(x.x, x.y);
        o.y = packh2(x.z, x.w);
        ((uint2*)dst)[i] = o;
    }
}

// ============================================================================
// Weight transpose: g_Wth[which][h*64+d][e] = fp16(W[which][h][e][d])
// ============================================================================
__global__ __launch_bounds__(256) void transpose_w_kernel(
    const float* __restrict__ Wq, const float* __restrict__ Wk,
    const float* __restrict__ Wv)
{
    __shared__ float tile[64][65];
    const int which = blockIdx.z;
    const int h     = blockIdx.y;
    const int e0    = blockIdx.x * 64;
    const float* W = (which == 0 ? Wq : (which == 1 ? Wk : Wv)) + (size_t)h * E_ * 64;
    const int tid = threadIdx.x;

#pragma unroll
    for (int u = 0; u < 16; u++) {
        int idx = tid + u * 256;
        int r = idx >> 6, c = idx & 63;
        tile[r][c] = W[(size_t)(e0 + r) * 64 + c];
    }
    __syncthreads();

    __half* out = g_Wth + (size_t)which * E_ * E_;
#pragma unroll
    for (int u = 0; u < 16; u++) {
        int idx = tid + u * 256;
        int d = idx >> 6, ee = idx & 63;
        out[(size_t)(h * 64 + d) * E_ + e0 + ee] = __float2half_rn(tile[ee][d]);
    }
}

// ============================================================================
// fp16 GEMM core (cp.async 3-stage, ldmatrix fragments):
// C[128,128] = A[128,K=1024] @ B[128,K=1024]^T, BK=32 (2 k16 steps).
// 256 threads / 8 warps (4M x 2N), warp tile 32x64.
// smem row = 40 halves (20 words): 8 rows x stride-20 hit all 32 banks once
// -> LDSM conflict-free for both k-lo (+0) and k-hi (+4) column offsets.
// ============================================================================
#define HLD 20
#define GSW (128 * HLD)
#define GEMM_SMEM_BYTES (6 * GSW * 4)        // 61440

__device__ __forceinline__ void gemm_issue_h(
    const __half* __restrict__ A, const __half* __restrict__ Bm,
    uint32_t su, int c, int s, int tid)
{
    const __half* Ac = A + (c << 5);
    const __half* Bc = Bm + (c << 5);
    const uint32_t ab = su + (uint32_t)s * GSW * 4;
    const uint32_t bb = su + (uint32_t)(3 + s) * GSW * 4;
#pragma unroll
    for (int u = 0; u < 2; u++) {
        int idx = tid + (u << 8);           // 0..511
        int r = idx >> 2, qq = idx & 3;
        uint32_t so = (uint32_t)r * 80 + (uint32_t)qq * 16;
        cp16(ab + so, Ac + (size_t)r * E_ + (qq << 3));
        cp16(bb + so, Bc + (size_t)r * E_ + (qq << 3));
    }
    CP_COMMIT;
}

__device__ __forceinline__ void gemm_tile_h(
    const __half* __restrict__ A, const __half* __restrict__ Bm,
    uint32_t* smw, float C[2][8][4])
{
    const int tid = threadIdx.x, wid = tid >> 5, lane = tid & 31;
    const int mw = (wid & 3) * 32, nw = (wid >> 2) * 64;
    const int i0 = lane & 7, sel = lane >> 3;
    const uint32_t su = smem_u32(smw);

    // per-lane ldmatrix word offsets (sel bit0 -> +8 rows for A / +4 words for B,
    // sel bit1 -> +4 words for A / +8 rows for B); see fragment-map derivation.
    const int arow = (mw + i0 + ((sel & 1) << 3)) * HLD + ((sel >> 1) << 2);
    int brow[4];
#pragma unroll
    for (int p = 0; p < 4; p++)
        brow[p] = (nw + 16 * p + ((sel >> 1) << 3) + i0) * HLD + ((sel & 1) << 2);

#pragma unroll
    for (int i = 0; i < 2; i++)
#pragma unroll
        for (int j = 0; j < 8; j++)
#pragma unroll
            for (int p = 0; p < 4; p++) C[i][j][p] = 0.f;

    gemm_issue_h(A, Bm, su, 0, 0, tid);
    gemm_issue_h(A, Bm, su, 1, 1, tid);

    int s = 0;
    for (int c = 0; c < 32; c++) {
        if (c < 31) { CP_WAIT1; } else { CP_WAIT0; }
        __syncthreads();
        if (c + 2 < 32) {
            int sn = s + 2; if (sn >= 3) sn -= 3;
            gemm_issue_h(A, Bm, su, c + 2, sn, tid);
        }
        const uint32_t aBase = su + (uint32_t)s * (GSW * 4);
        const uint32_t bBase = su + (uint32_t)(3 + s) * (GSW * 4);
#pragma unroll
        for (int ks = 0; ks < 2; ks++) {
            const int ko = ks * 8;
            uint32_t af[2][4], bf[4][4];
            ldsm4(af[0], aBase + (uint32_t)(arow + ko) * 4);
            ldsm4(af[1], aBase + (uint32_t)(arow + 16 * HLD + ko) * 4);
#pragma unroll
            for (int p = 0; p < 4; p++)
                ldsm4(bf[p], bBase + (uint32_t)(brow[p] + ko) * 4);
#pragma unroll
            for (int i = 0; i < 2; i++)
#pragma unroll
                for (int p = 0; p < 4; p++) {
                    mma16h(C[i][2 * p],     af[i], &bf[p][0]);
                    mma16h(C[i][2 * p + 1], af[i], &bf[p][2]);
                }
        }
        if (++s == 3) s = 0;
    }
}

// ============================================================================
// QKV projection: grid (T/128, E/128, 12 = which*4+b).
// Epilogue packs fp16x2 and scatters into fragment blobs. Q stays UNscaled.
// ============================================================================
__global__ __launch_bounds__(256, 2) void proj_mma_kernel()
{
    extern __shared__ uint32_t gsm[];
    const int which = blockIdx.z >> 2;
    const int b     = blockIdx.z & 3;
    const int t0    = blockIdx.x * 128;
    const int n0    = blockIdx.y * 128;
    const __half* X  = g_Xh + ((size_t)which * B_ + b) * T_ * E_ + (size_t)t0 * E_;
    const __half* Bm = g_Wth + (size_t)which * E_ * E_ + (size_t)n0 * E_;

    float C[2][8][4];
    gemm_tile_h(X, Bm, gsm, C);

    const int lane = threadIdx.x & 31, wid = threadIdx.x >> 5;
    const int ge = lane >> 2, te = lane & 3;
    const int mw = (wid & 3) * 32, nw = (wid >> 2) * 64;

#pragma unroll
    for (int i = 0; i < 2; i++) {
        const int t_lo = t0 + mw + 16 * i + ge;
#pragma unroll
        for (int j = 0; j < 8; j++) {
            const int c  = n0 + nw + 8 * j + 2 * te;
            const int h  = c >> 6, d = c & 63;
            const int bh = b * 16 + h;

            if (which == 0) {
                uint32_t w01 = packh2(C[i][j][0], C[i][j][1]);
                uint32_t w23 = packh2(C[i][j][2], C[i][j][3]);
                int qb = t_lo >> 7, tl = t_lo & 127;
                int rb = tl >> 4, gp = tl & 7;
                int ks = d >> 4, dk = d & 15;
                int tgp = (dk >> 1) & 3, rhi = (dk >> 3) << 1;
                size_t idx = ((size_t)bh * 16 + qb) * 4096 +
                             (size_t)(((ks * 8 + rb) * 32 + 4 * gp + tgp) * 4 + rhi);
                uint2 st; st.x = w01; st.y = w23;
                *(uint2*)&g_Qfh[idx] = st;
            } else if (which == 1) {
                uint32_t w01 = packh2(C[i][j][0], C[i][j][1]);
                uint32_t w23 = packh2(C[i][j][2], C[i][j][3]);
                int kt = t_lo >> 6, sidx = t_lo & 63;
                int jp = sidx >> 3, gp = sidx & 7;
                int ks = d >> 4, dk = d & 15;
                int reg = dk >> 3, tgp = (dk >> 1) & 3;
                size_t base = ((size_t)bh * 32 + kt) * 2048;
                g_Kfh[base + ((ks * 8 + jp) * 32 + 4 * gp + tgp) * 2 + reg] = w01;
                g_Kfh[base + ((ks * 8 + jp + 1) * 32 + 4 * gp + tgp) * 2 + reg] = w23;
            } else {
                float q0 = __shfl_xor_sync(0xffffffffu, C[i][j][0], 4);
                float q1 = __shfl_xor_sync(0xffffffffu, C[i][j][1], 4);
                float q2 = __shfl_xor_sync(0xffffffffu, C[i][j][2], 4);
                float q3 = __shfl_xor_sync(0xffffffffu, C[i][j][3], 4);
                if ((ge & 1) == 0) {
                    uint32_t wA = packh2(C[i][j][0], q0);
                    uint32_t wB = packh2(C[i][j][1], q1);
                    uint32_t wC = packh2(C[i][j][2], q2);
                    uint32_t wD = packh2(C[i][j][3], q3);
                    int kt = t_lo >> 6, sidx = t_lo & 63;
                    int ks = sidx >> 4, sk = sidx & 15;
                    int tgp = (sk >> 1) & 3;
                    int jp = d >> 3, gp = d & 7;
                    size_t base = ((size_t)bh * 32 + kt) * 2048;
                    size_t iA = base + ((ks * 8 + jp) * 32 + 4 * gp + tgp) * 2;
                    size_t iB = base + ((ks * 8 + jp) * 32 + 4 * (gp + 1) + tgp) * 2;
                    uint2 s0; s0.x = wA; s0.y = wC;
                    uint2 s1; s1.x = wB; s1.y = wD;
                    *(uint2*)&g_Vfh[iA] = s0;
                    *(uint2*)&g_Vfh[iB] = s1;
                }
            }
        }
    }
}

// ============================================================================
// Output projection: out = attn(fp16) @ Wp(fp16)^T + bp (fp32 epilogue).
// ============================================================================
__global__ __launch_bounds__(256, 2) void outproj_mma_kernel(
    const float* __restrict__ bp, float* __restrict__ out)
{
    extern __shared__ uint32_t gsm[];
    const int m0 = blockIdx.x * 128;
    const int n0 = blockIdx.y * 128;

    float C[2][8][4];
    gemm_tile_h(g_attnh + (size_t)m0 * E_, g_Wph + (size_t)n0 * E_, gsm, C);

    const int lane = threadIdx.x & 31, wid = threadIdx.x >> 5;
    const int g = lane >> 2, tg = lane & 3;
    const int mw = (wid & 3) * 32, nw = (wid >> 2) * 64;

#pragma unroll
    for (int i = 0; i < 2; i++) {
        size_t r = (size_t)(m0 + mw + 16 * i + g);
#pragma unroll
        for (int j = 0; j < 8; j++) {
            int cc = n0 + nw + 8 * j + 2 * tg;
            float2 bv = *(const float2*)&bp[cc];
            float2 v0 = {C[i][j][0] + bv.x, C[i][j][1] + bv.y};
            float2 v1 = {C[i][j][2] + bv.x, C[i][j][3] + bv.y};
            *(float2*)&out[r * E_ + cc] = v0;
            *(float2*)&out[(r + 8) * E_ + cc] = v1;
        }
    }
}

// ============================================================================
// Causal flash attention, fp16 m16n8k16, log2-domain online softmax.
// 128-row CTA, 4 warps x 32 rows. Q blob once; K,V double-buffered.
// P = ex2(fma(S, c2, -m2)) with c2 = log2(e)/32 — one FFMA + one MUFU per elt.
// grid (T/128, B*H), 128 threads.
// ============================================================================
#define FQW 4096
#define FKW 2048
#define FLASH_SMEM_BYTES ((FQW + 2 * FKW + 2 * FKW) * 4)   // 49152
#define C2F 0.0450844331f   // log2(e) / 32

__global__ __launch_bounds__(128, 2) void flash_mma_kernel()
{
    extern __shared__ uint32_t smf[];
    uint32_t* Qs  = smf;
    uint32_t* Ks2 = smf + FQW;
    uint32_t* Vs2 = smf + FQW + 2 * FKW;

    const int bh = blockIdx.y;
    const int b  = bh >> 4, h = bh & 15;
    const int qb = gridDim.x - 1 - blockIdx.x;
    const int tid = threadIdx.x, w = tid >> 5, lane = tid & 31;
    const int g = lane >> 2, tg = lane & 3;
    const int last = 2 * qb + 1;

    const uint32_t* Qg = g_Qfh + ((size_t)bh * 16 + qb) * FQW;
    const uint32_t* Kg = g_Kfh + (size_t)bh * 32 * FKW;
    const uint32_t* Vg = g_Vfh + (size_t)bh * 32 * FKW;

    const uint32_t qs_u = smem_u32(Qs);
    const uint32_t ks_u = smem_u32(Ks2);
    const uint32_t vs_u = smem_u32(Vs2);

    auto issueKV = [&](int kt) {
        const uint32_t kb = ks_u + (uint32_t)((kt & 1) * FKW * 4);
        const uint32_t vb = vs_u + (uint32_t)((kt & 1) * FKW * 4);
        const uint32_t* Kp = Kg + (size_t)kt * FKW;
        const uint32_t* Vp = Vg + (size_t)kt * FKW;
#pragma unroll
        for (int u = 0; u < 4; u++) {
            int idx = tid + (u << 7);
            cp16(kb + (uint32_t)idx * 16, Kp + (size_t)idx * 4);
            cp16(vb + (uint32_t)idx * 16, Vp + (size_t)idx * 4);
        }
        CP_COMMIT;
    };

    {
#pragma unroll
        for (int u = 0; u < 8; u++) {
            int idx = tid + (u << 7);
            cp16(qs_u + (uint32_t)idx * 16, Qg + (size_t)idx * 4);
        }
#pragma unroll
        for (int u = 0; u < 4; u++) {
            int idx = tid + (u << 7);
            cp16(ks_u + (uint32_t)idx * 16, Kg + (size_t)idx * 4);
            cp16(vs_u + (uint32_t)idx * 16, Vg + (size_t)idx * 4);
        }
        CP_COMMIT;
        if (last >= 1) issueKV(1);
    }

    uint32_t qf[2][4][4];
    float O[2][8][4];
    float m_s[2][2], l_s[2][2];
#pragma unroll
    for (int i = 0; i < 2; i++) {
#pragma unroll
        for (int hf = 0; hf < 2; hf++) { m_s[i][hf] = -INFINITY; l_s[i][hf] = 0.f; }
#pragma unroll
        for (int j = 0; j < 8; j++)
#pragma unroll
            for (int p = 0; p < 4; p++) O[i][j][p] = 0.f;
    }

    const int wr = qb * 128 + 32 * w;

    for (int kt = 0; kt <= last; kt++) {
        if (kt < last) { CP_WAIT1; } else { CP_WAIT0; }
        __syncthreads();

        if (kt == 0) {
            const uint4* Qf4 = (const uint4*)Qs;
#pragma unroll
            for (int ks = 0; ks < 4; ks++)
#pragma unroll
                for (int i = 0; i < 2; i++) {
                    uint4 qa = Qf4[(ks * 8 + 2 * w + i) * 32 + lane];
                    qf[i][ks][0] = qa.x; qf[i][ks][1] = qa.y;
                    qf[i][ks][2] = qa.z; qf[i][ks][3] = qa.w;
                }
        }

        const uint2* Kf = (const uint2*)(Ks2 + (size_t)(kt & 1) * FKW);
        const uint2* Vf = (const uint2*)(Vs2 + (size_t)(kt & 1) * FKW);

        // ---- S = Q @ K^T (raw, unscaled) ----
        float S[2][8][4];
#pragma unroll
        for (int i = 0; i < 2; i++)
#pragma unroll
            for (int j = 0; j < 8; j++)
#pragma unroll
                for (int p = 0; p < 4; p++) S[i][j][p] = 0.f;

#pragma unroll
        for (int ks = 0; ks < 4; ks++)
#pragma unroll
            for (int j = 0; j < 8; j++) {
                uint2 kb = Kf[(ks * 8 + j) * 32 + lane];
                uint32_t bb[2] = {kb.x, kb.y};
                mma16h(S[0][j], qf[0][ks], bb);
                mma16h(S[1][j], qf[1][ks], bb);
            }

        // ---- causal mask (last two tiles only) ----
        if (kt >= 2 * qb) {
            const int kb0 = kt * 64;
#pragma unroll
            for (int i = 0; i < 2; i++) {
                int r0 = wr + 16 * i + g;
#pragma unroll
                for (int j = 0; j < 8; j++) {
                    int c0 = kb0 + 8 * j + 2 * tg;
                    if (c0 > r0)         S[i][j][0] = -INFINITY;
                    if (c0 + 1 > r0)     S[i][j][1] = -INFINITY;
                    if (c0 > r0 + 8)     S[i][j][2] = -INFINITY;
                    if (c0 + 1 > r0 + 8) S[i][j][3] = -INFINITY;
                }
            }
        }

        // ---- online softmax in log2-scaled domain ----
#pragma unroll
        for (int i = 0; i < 2; i++) {
            float rm0 = -INFINITY, rm1 = -INFINITY;
#pragma unroll
            for (int j = 0; j < 8; j++) {
                rm0 = fmaxf(rm0, fmaxf(S[i][j][0], S[i][j][1]));
                rm1 = fmaxf(rm1, fmaxf(S[i][j][2], S[i][j][3]));
            }
            rm0 = fmaxf(rm0, __shfl_xor_sync(0xffffffffu, rm0, 1));
            rm0 = fmaxf(rm0, __shfl_xor_sync(0xffffffffu, rm0, 2));
            rm1 = fmaxf(rm1, __shfl_xor_sync(0xffffffffu, rm1, 1));
            rm1 = fmaxf(rm1, __shfl_xor_sync(0xffffffffu, rm1, 2));

            float mn0 = fmaxf(m_s[i][0], rm0 * C2F);
            float mn1 = fmaxf(m_s[i][1], rm1 * C2F);
            float a0 = ex2f(m_s[i][0] - mn0), a1 = ex2f(m_s[i][1] - mn1);
            float s0 = 0.f, s1 = 0.f;
#pragma unroll
            for (int j = 0; j < 8; j++) {
                S[i][j][0] = ex2f(fmaf(S[i][j][0], C2F, -mn0));
                S[i][j][1] = ex2f(fmaf(S[i][j][1], C2F, -mn0));
                S[i][j][2] = ex2f(fmaf(S[i][j][2], C2F, -mn1));
                S[i][j][3] = ex2f(fmaf(S[i][j][3], C2F, -mn1));
                s0 += S[i][j][0] + S[i][j][1];
                s1 += S[i][j][2] + S[i][j][3];
            }
            s0 += __shfl_xor_sync(0xffffffffu, s0, 1);
            s0 += __shfl_xor_sync(0xffffffffu, s0, 2);
            s1 += __shfl_xor_sync(0xffffffffu, s1, 1);
            s1 += __shfl_xor_sync(0xffffffffu, s1, 2);
            l_s[i][0] = l_s[i][0] * a0 + s0;
            l_s[i][1] = l_s[i][1] * a1 + s1;
            m_s[i][0] = mn0;
            m_s[i][1] = mn1;
#pragma unroll
            for (int j = 0; j < 8; j++) {
                O[i][j][0] *= a0; O[i][j][1] *= a0;
                O[i][j][2] *= a1; O[i][j][3] *= a1;
            }
        }

        // ---- O += P @ V : C-frag packed to fp16x2 A-frags (FA2 trick) ----
#pragma unroll
        for (int ks = 0; ks < 4; ks++) {
            uint32_t ap[2][4];
#pragma unroll
            for (int i = 0; i < 2; i++) {
                ap[i][0] = packh2(S[i][2 * ks][0],     S[i][2 * ks][1]);
                ap[i][1] = packh2(S[i][2 * ks][2],     S[i][2 * ks][3]);
                ap[i][2] = packh2(S[i][2 * ks + 1][0], S[i][2 * ks + 1][1]);
                ap[i][3] = packh2(S[i][2 * ks + 1][2], S[i][2 * ks + 1][3]);
            }
#pragma unroll
            for (int j = 0; j < 8; j++) {
                uint2 vb = Vf[(ks * 8 + j) * 32 + lane];
                uint32_t bb[2] = {vb.x, vb.y};
                mma16h(O[0][j], ap[0], bb);
                mma16h(O[1][j], ap[1], bb);
            }
        }

        __syncthreads();
        if (kt + 2 <= last) issueKV(kt + 2);
    }

    // ---- epilogue: normalize, pack fp16, write row-major [B,T,E] ----
#pragma unroll
    for (int i = 0; i < 2; i++) {
        float inv0 = 1.f / l_s[i][0], inv1 = 1.f / l_s[i][1];
        int row = wr + 16 * i + g;
        uint32_t* o0 = (uint32_t*)g_attnh + ((size_t)b * T_ + row) * (E_ / 2) + h * 32;
        uint32_t* o1 = o0 + 8 * (E_ / 2);
#pragma unroll
        for (int j = 0; j < 8; j++) {
            o0[4 * j + tg] = packh2(O[i][j][0] * inv0, O[i][j][1] * inv0);
            o1[4 * j + tg] = packh2(O[i][j][2] * inv1, O[i][j][3] * inv1);
        }
    }
}

// ============================================================================
extern "C" void kernel_launch(void* const* d_in, const int* in_sizes, int n_in,
                              void* d_out, int out_size)
{
    // metadata order: k, q, v, mask, Wk, Wq, Wv, Wp, bp
    const float* k  = (const float*)d_in[0];
    const float* q  = (const float*)d_in[1];
    const float* v  = (const float*)d_in[2];
    const float* Wk = (const float*)d_in[4];
    const float* Wq = (const float*)d_in[5];
    const float* Wv = (const float*)d_in[6];
    const float* Wp = (const float*)d_in[7];
    const float* bp = (const float*)d_in[8];
    float* out = (float*)d_out;

    cudaFuncSetAttribute(proj_mma_kernel,
                         cudaFuncAttributeMaxDynamicSharedMemorySize, GEMM_SMEM_BYTES);
    cudaFuncSetAttribute(outproj_mma_kernel,
                         cudaFuncAttributeMaxDynamicSharedMemorySize, GEMM_SMEM_BYTES);
    cudaFuncSetAttribute(flash_mma_kernel,
                         cudaFuncAttributeMaxDynamicSharedMemorySize, FLASH_SMEM_BYTES);

    cvt_h_kernel<<<dim3(8192, 4), 256>>>(q, k, v, Wp);

    transpose_w_kernel<<<dim3(E_ / 64, H_, 3), 256>>>(Wq, Wk, Wv);

    proj_mma_kernel<<<dim3(T_ / 128, E_ / 128, 12), 256, GEMM_SMEM_BYTES>>>();

    flash_mma_kernel<<<dim3(T_ / 128, B_ * H_), 128, FLASH_SMEM_BYTES>>>();

    outproj_mma_kernel<<<dim3((B_ * T_) / 128, E_ / 128), 256, GEMM_SMEM_BYTES>>>(bp, out);
}

// round 9
// speedup vs baseline: 2.0849x; 1.0690x over previous
#include <cuda_runtime.h>
#include <cuda_fp16.h>
#include <math.h>
#include <stdint.h>

#define B_ 4
#define T_ 2048
#define E_ 1024
#define H_ 16

// Device-global scratch (allocation-free).
__device__ __half   g_Xh[(size_t)3 * B_ * T_ * E_];
__device__ __half   g_Wph[(size_t)E_ * E_];
__device__ __half   g_Wth[(size_t)3 * E_ * E_];
__device__ uint32_t g_Qfh[(size_t)64 * 16 * 4096];
__device__ uint32_t g_Kfh[(size_t)64 * 32 * 2048];
__device__ uint32_t g_Vfh[(size_t)64 * 32 * 2048];
__device__ __half   g_attnh[(size_t)B_ * T_ * E_];

// ============================================================================
// Helpers
// ============================================================================
__device__ __forceinline__ uint32_t packh2(float lo, float hi) {
    uint32_t r;
    asm("cvt.rn.f16x2.f32 %0, %1, %2;" : "=r"(r) : "f"(hi), "f"(lo));
    return r;
}

__device__ __forceinline__ float ex2f(float x) {
    float y;
    asm("ex2.approx.f32 %0, %1;" : "=f"(y) : "f"(x));
    return y;
}

__device__ __forceinline__ uint32_t smem_u32(const void* p) {
    uint32_t a;
    asm("{ .reg .u64 t; cvta.to.shared.u64 t, %1; cvt.u32.u64 %0, t; }"
        : "=r"(a) : "l"(p));
    return a;
}

// D(16x8,f32) += A(16x16,f16) * B(16x8,f16)
__device__ __forceinline__ void mma16h(float* c, const uint32_t* a, const uint32_t* b) {
    asm volatile(
        "mma.sync.aligned.m16n8k16.row.col.f32.f16.f16.f32 "
        "{%0,%1,%2,%3}, {%4,%5,%6,%7}, {%8,%9}, {%0,%1,%2,%3};"
        : "+f"(c[0]), "+f"(c[1]), "+f"(c[2]), "+f"(c[3])
        : "r"(a[0]), "r"(a[1]), "r"(a[2]), "r"(a[3]), "r"(b[0]), "r"(b[1]));
}

__device__ __forceinline__ void ldsm4(uint32_t* r, uint32_t a) {
    asm volatile("ldmatrix.sync.aligned.m8n8.x4.shared.b16 {%0,%1,%2,%3}, [%4];"
                 : "=r"(r[0]), "=r"(r[1]), "=r"(r[2]), "=r"(r[3]) : "r"(a));
}

__device__ __forceinline__ void cp16(uint32_t dst, const void* src) {
    asm volatile("cp.async.cg.shared.global [%0], [%1], 16;"
                 :: "r"(dst), "l"(src));
}
#define CP_COMMIT asm volatile("cp.async.commit_group;" ::: "memory")
#define CP_WAIT0  asm volatile("cp.async.wait_group 0;" ::: "memory")
#define CP_WAIT1  asm volatile("cp.async.wait_group 1;" ::: "memory")

// ============================================================================
// Convert pass: g_Xh[z] = fp16(q|k|v), g_Wph = fp16(Wp)
// ============================================================================
__global__ __launch_bounds__(256) void cvt_h_kernel(
    const float* __restrict__ q, const float* __restrict__ k,
    const float* __restrict__ v, const float* __restrict__ Wp)
{
    const int z = blockIdx.y;
    const float* src;
    __half* dst;
    size_t n4;
    if (z < 3) {
        src = (z == 0 ? q : (z == 1 ? k : v));
        dst = g_Xh + (size_t)z * B_ * T_ * E_;
        n4  = (size_t)B_ * T_ * E_ / 4;
    } else {
        src = Wp;
        dst = g_Wph;
        n4  = (size_t)E_ * E_ / 4;
    }
    size_t i = (size_t)blockIdx.x * 256 + threadIdx.x;
    if (i < n4) {
        float4 x = ((const float4*)src)[i];
        uint2 o;
        o.x = packh2(x.x, x.y);
        o.y = packh2(x.z, x.w);
        ((uint2*)dst)[i] = o;
    }
}

// ============================================================================
// Weight transpose: g_Wth[which][h*64+d][e] = fp16(W[which][h][e][d])
// ============================================================================
__global__ __launch_bounds__(256) void transpose_w_kernel(
    const float* __restrict__ Wq, const float* __restrict__ Wk,
    const float* __restrict__ Wv)
{
    __shared__ float tile[64][65];
    const int which = blockIdx.z;
    const int h     = blockIdx.y;
    const int e0    = blockIdx.x * 64;
    const float* W = (which == 0 ? Wq : (which == 1 ? Wk : Wv)) + (size_t)h * E_ * 64;
    const int tid = threadIdx.x;

#pragma unroll
    for (int u = 0; u < 16; u++) {
        int idx = tid + u * 256;
        int r = idx >> 6, c = idx & 63;
        tile[r][c] = W[(size_t)(e0 + r) * 64 + c];
    }
    __syncthreads();

    __half* out = g_Wth + (size_t)which * E_ * E_;
#pragma unroll
    for (int u = 0; u < 16; u++) {
        int idx = tid + u * 256;
        int d = idx >> 6, ee = idx & 63;
        out[(size_t)(h * 64 + d) * E_ + e0 + ee] = __float2half_rn(tile[ee][d]);
    }
}

// ============================================================================
// fp16 GEMM core (cp.async 3-stage, ldmatrix, BK=64):
// C[128,128] = A[128,K=1024] @ B[128,K=1024]^T, 16 chunks of 64 (4 k16 steps).
// 256 threads / 8 warps (4M x 2N), warp tile 32x64.
// smem row = 72 halves (36 words): 8 rows x stride-36 -> phases 4r mod 32,
// all distinct -> LDSM conflict-free at every k offset.
// ============================================================================
#define HLD 36
#define GSW (128 * HLD)
#define GEMM_SMEM_BYTES (6 * GSW * 4)        // 110592

__device__ __forceinline__ void gemm_issue_h(
    const __half* __restrict__ A, const __half* __restrict__ Bm,
    uint32_t su, int c, int s, int tid)
{
    const __half* Ac = A + (c << 6);
    const __half* Bc = Bm + (c << 6);
    const uint32_t ab = su + (uint32_t)s * GSW * 4;
    const uint32_t bb = su + (uint32_t)(3 + s) * GSW * 4;
#pragma unroll
    for (int u = 0; u < 4; u++) {
        int idx = tid + (u << 8);           // 0..1023
        int r = idx >> 3, qq = idx & 7;
        uint32_t so = (uint32_t)r * 144 + (uint32_t)qq * 16;
        cp16(ab + so, Ac + (size_t)r * E_ + (qq << 3));
        cp16(bb + so, Bc + (size_t)r * E_ + (qq << 3));
    }
    CP_COMMIT;
}

__device__ __forceinline__ void gemm_tile_h(
    const __half* __restrict__ A, const __half* __restrict__ Bm,
    uint32_t* smw, float C[2][8][4])
{
    const int tid = threadIdx.x, wid = tid >> 5, lane = tid & 31;
    const int mw = (wid & 3) * 32, nw = (wid >> 2) * 64;
    const int i0 = lane & 7, sel = lane >> 3;
    const uint32_t su = smem_u32(smw);

    const int arow = (mw + i0 + ((sel & 1) << 3)) * HLD + ((sel >> 1) << 2);
    int brow[4];
#pragma unroll
    for (int p = 0; p < 4; p++)
        brow[p] = (nw + 16 * p + ((sel >> 1) << 3) + i0) * HLD + ((sel & 1) << 2);

#pragma unroll
    for (int i = 0; i < 2; i++)
#pragma unroll
        for (int j = 0; j < 8; j++)
#pragma unroll
            for (int p = 0; p < 4; p++) C[i][j][p] = 0.f;

    gemm_issue_h(A, Bm, su, 0, 0, tid);
    gemm_issue_h(A, Bm, su, 1, 1, tid);

    int s = 0;
    for (int c = 0; c < 16; c++) {
        if (c < 15) { CP_WAIT1; } else { CP_WAIT0; }
        __syncthreads();
        if (c + 2 < 16) {
            int sn = s + 2; if (sn >= 3) sn -= 3;
            gemm_issue_h(A, Bm, su, c + 2, sn, tid);
        }
        const uint32_t aBase = su + (uint32_t)s * (GSW * 4);
        const uint32_t bBase = su + (uint32_t)(3 + s) * (GSW * 4);
#pragma unroll
        for (int ks = 0; ks < 4; ks++) {
            const int ko = ks * 8;
            uint32_t af[2][4], bf[4][4];
            ldsm4(af[0], aBase + (uint32_t)(arow + ko) * 4);
            ldsm4(af[1], aBase + (uint32_t)(arow + 16 * HLD + ko) * 4);
#pragma unroll
            for (int p = 0; p < 4; p++)
                ldsm4(bf[p], bBase + (uint32_t)(brow[p] + ko) * 4);
#pragma unroll
            for (int i = 0; i < 2; i++)
#pragma unroll
                for (int p = 0; p < 4; p++) {
                    mma16h(C[i][2 * p],     af[i], &bf[p][0]);
                    mma16h(C[i][2 * p + 1], af[i], &bf[p][2]);
                }
        }
        if (++s == 3) s = 0;
    }
}

// ============================================================================
// QKV projection: grid (T/128, E/128, 12 = which*4+b).
// Epilogue packs fp16x2 and scatters into fragment blobs. Q stays UNscaled.
// ============================================================================
__global__ __launch_bounds__(256, 2) void proj_mma_kernel()
{
    extern __shared__ uint32_t gsm[];
    const int which = blockIdx.z >> 2;
    const int b     = blockIdx.z & 3;
    const int t0    = blockIdx.x * 128;
    const int n0    = blockIdx.y * 128;
    const __half* X  = g_Xh + ((size_t)which * B_ + b) * T_ * E_ + (size_t)t0 * E_;
    const __half* Bm = g_Wth + (size_t)which * E_ * E_ + (size_t)n0 * E_;

    float C[2][8][4];
    gemm_tile_h(X, Bm, gsm, C);

    const int lane = threadIdx.x & 31, wid = threadIdx.x >> 5;
    const int ge = lane >> 2, te = lane & 3;
    const int mw = (wid & 3) * 32, nw = (wid >> 2) * 64;

#pragma unroll
    for (int i = 0; i < 2; i++) {
        const int t_lo = t0 + mw + 16 * i + ge;
#pragma unroll
        for (int j = 0; j < 8; j++) {
            const int c  = n0 + nw + 8 * j + 2 * te;
            const int h  = c >> 6, d = c & 63;
            const int bh = b * 16 + h;

            if (which == 0) {
                uint32_t w01 = packh2(C[i][j][0], C[i][j][1]);
                uint32_t w23 = packh2(C[i][j][2], C[i][j][3]);
                int qb = t_lo >> 7, tl = t_lo & 127;
                int rb = tl >> 4, gp = tl & 7;
                int ks = d >> 4, dk = d & 15;
                int tgp = (dk >> 1) & 3, rhi = (dk >> 3) << 1;
                size_t idx = ((size_t)bh * 16 + qb) * 4096 +
                             (size_t)(((ks * 8 + rb) * 32 + 4 * gp + tgp) * 4 + rhi);
                uint2 st; st.x = w01; st.y = w23;
                *(uint2*)&g_Qfh[idx] = st;
            } else if (which == 1) {
                uint32_t w01 = packh2(C[i][j][0], C[i][j][1]);
                uint32_t w23 = packh2(C[i][j][2], C[i][j][3]);
                int kt = t_lo >> 6, sidx = t_lo & 63;
                int jp = sidx >> 3, gp = sidx & 7;
                int ks = d >> 4, dk = d & 15;
                int reg = dk >> 3, tgp = (dk >> 1) & 3;
                size_t base = ((size_t)bh * 32 + kt) * 2048;
                g_Kfh[base + ((ks * 8 + jp) * 32 + 4 * gp + tgp) * 2 + reg] = w01;
                g_Kfh[base + ((ks * 8 + jp + 1) * 32 + 4 * gp + tgp) * 2 + reg] = w23;
            } else {
                float q0 = __shfl_xor_sync(0xffffffffu, C[i][j][0], 4);
                float q1 = __shfl_xor_sync(0xffffffffu, C[i][j][1], 4);
                float q2 = __shfl_xor_sync(0xffffffffu, C[i][j][2], 4);
                float q3 = __shfl_xor_sync(0xffffffffu, C[i][j][3], 4);
                if ((ge & 1) == 0) {
                    uint32_t wA = packh2(C[i][j][0], q0);
                    uint32_t wB = packh2(C[i][j][1], q1);
                    uint32_t wC = packh2(C[i][j][2], q2);
                    uint32_t wD = packh2(C[i][j][3], q3);
                    int kt = t_lo >> 6, sidx = t_lo & 63;
                    int ks = sidx >> 4, sk = sidx & 15;
                    int tgp = (sk >> 1) & 3;
                    int jp = d >> 3, gp = d & 7;
                    size_t base = ((size_t)bh * 32 + kt) * 2048;
                    size_t iA = base + ((ks * 8 + jp) * 32 + 4 * gp + tgp) * 2;
                    size_t iB = base + ((ks * 8 + jp) * 32 + 4 * (gp + 1) + tgp) * 2;
                    uint2 s0; s0.x = wA; s0.y = wC;
                    uint2 s1; s1.x = wB; s1.y = wD;
                    *(uint2*)&g_Vfh[iA] = s0;
                    *(uint2*)&g_Vfh[iB] = s1;
                }
            }
        }
    }
}

// ============================================================================
// Output projection: out = attn(fp16) @ Wp(fp16)^T + bp (fp32 epilogue).
// ============================================================================
__global__ __launch_bounds__(256, 2) void outproj_mma_kernel(
    const float* __restrict__ bp, float* __restrict__ out)
{
    extern __shared__ uint32_t gsm[];
    const int m0 = blockIdx.x * 128;
    const int n0 = blockIdx.y * 128;

    float C[2][8][4];
    gemm_tile_h(g_attnh + (size_t)m0 * E_, g_Wph + (size_t)n0 * E_, gsm, C);

    const int lane = threadIdx.x & 31, wid = threadIdx.x >> 5;
    const int g = lane >> 2, tg = lane & 3;
    const int mw = (wid & 3) * 32, nw = (wid >> 2) * 64;

#pragma unroll
    for (int i = 0; i < 2; i++) {
        size_t r = (size_t)(m0 + mw + 16 * i + g);
#pragma unroll
        for (int j = 0; j < 8; j++) {
            int cc = n0 + nw + 8 * j + 2 * tg;
            float2 bv = *(const float2*)&bp[cc];
            float2 v0 = {C[i][j][0] + bv.x, C[i][j][1] + bv.y};
            float2 v1 = {C[i][j][2] + bv.x, C[i][j][3] + bv.y};
            *(float2*)&out[r * E_ + cc] = v0;
            *(float2*)&out[(r + 8) * E_ + cc] = v1;
        }
    }
}

// ============================================================================
// Causal flash attention, fp16 m16n8k16, log2-domain online softmax.
// 128-row CTA, 4 warps x 32 rows. Q blob once; K,V TRIPLE-buffered ->
// ONE __syncthreads per iteration. l accumulated by an extra ones-column
// PV MMA (same rescale chain as O) — no per-tile sum reduction at all.
// grid (T/128, B*H), 128 threads.
// ============================================================================
#define FQW 4096
#define FKW 2048
#define FLASH_SMEM_BYTES ((FQW + 3 * FKW + 3 * FKW) * 4)   // 65536
#define C2F 0.0450844331f   // log2(e) / 32
#define ONESH2 0x3C003C00u  // fp16x2 {1,1}

__global__ __launch_bounds__(128, 2) void flash_mma_kernel()
{
    extern __shared__ uint32_t smf[];
    uint32_t* Qs  = smf;
    uint32_t* Ks3 = smf + FQW;
    uint32_t* Vs3 = smf + FQW + 3 * FKW;

    const int bh = blockIdx.y;
    const int b  = bh >> 4, h = bh & 15;
    const int qb = gridDim.x - 1 - blockIdx.x;
    const int tid = threadIdx.x, w = tid >> 5, lane = tid & 31;
    const int g = lane >> 2, tg = lane & 3;
    const int last = 2 * qb + 1;

    const uint32_t* Qg = g_Qfh + ((size_t)bh * 16 + qb) * FQW;
    const uint32_t* Kg = g_Kfh + (size_t)bh * 32 * FKW;
    const uint32_t* Vg = g_Vfh + (size_t)bh * 32 * FKW;

    const uint32_t qs_u = smem_u32(Qs);
    const uint32_t ks_u = smem_u32(Ks3);
    const uint32_t vs_u = smem_u32(Vs3);

    auto issueKV = [&](int kt) {
        int st = kt % 3;
        const uint32_t kb = ks_u + (uint32_t)(st * FKW * 4);
        const uint32_t vb = vs_u + (uint32_t)(st * FKW * 4);
        const uint32_t* Kp = Kg + (size_t)kt * FKW;
        const uint32_t* Vp = Vg + (size_t)kt * FKW;
#pragma unroll
        for (int u = 0; u < 4; u++) {
            int idx = tid + (u << 7);
            cp16(kb + (uint32_t)idx * 16, Kp + (size_t)idx * 4);
            cp16(vb + (uint32_t)idx * 16, Vp + (size_t)idx * 4);
        }
        CP_COMMIT;
    };

    {
#pragma unroll
        for (int u = 0; u < 8; u++) {
            int idx = tid + (u << 7);
            cp16(qs_u + (uint32_t)idx * 16, Qg + (size_t)idx * 4);
        }
#pragma unroll
        for (int u = 0; u < 4; u++) {
            int idx = tid + (u << 7);
            cp16(ks_u + (uint32_t)idx * 16, Kg + (size_t)idx * 4);
            cp16(vs_u + (uint32_t)idx * 16, Vg + (size_t)idx * 4);
        }
        CP_COMMIT;
        if (last >= 1) issueKV(1);
    }

    uint32_t qf[2][4][4];
    float O[2][8][4];
    float Ol[2][4];                 // ones-column accumulators (l in [0],[2])
    float m_s[2][2];
#pragma unroll
    for (int i = 0; i < 2; i++) {
        m_s[i][0] = -INFINITY; m_s[i][1] = -INFINITY;
#pragma unroll
        for (int p = 0; p < 4; p++) Ol[i][p] = 0.f;
#pragma unroll
        for (int j = 0; j < 8; j++)
#pragma unroll
            for (int p = 0; p < 4; p++) O[i][j][p] = 0.f;
    }

    const int wr = qb * 128 + 32 * w;
    const uint32_t ones_bb[2] = {ONESH2, ONESH2};

    for (int kt = 0; kt <= last; kt++) {
        if (kt < last) { CP_WAIT1; } else { CP_WAIT0; }
        __syncthreads();
        if (kt + 2 <= last) issueKV(kt + 2);

        if (kt == 0) {
            const uint4* Qf4 = (const uint4*)Qs;
#pragma unroll
            for (int ks = 0; ks < 4; ks++)
#pragma unroll
                for (int i = 0; i < 2; i++) {
                    uint4 qa = Qf4[(ks * 8 + 2 * w + i) * 32 + lane];
                    qf[i][ks][0] = qa.x; qf[i][ks][1] = qa.y;
                    qf[i][ks][2] = qa.z; qf[i][ks][3] = qa.w;
                }
        }

        const int st = kt % 3;
        const uint2* Kf = (const uint2*)(Ks3 + (size_t)st * FKW);
        const uint2* Vf = (const uint2*)(Vs3 + (size_t)st * FKW);

        // ---- S = Q @ K^T (raw, unscaled) ----
        float S[2][8][4];
#pragma unroll
        for (int i = 0; i < 2; i++)
#pragma unroll
            for (int j = 0; j < 8; j++)
#pragma unroll
                for (int p = 0; p < 4; p++) S[i][j][p] = 0.f;

#pragma unroll
        for (int ks = 0; ks < 4; ks++)
#pragma unroll
            for (int j = 0; j < 8; j++) {
                uint2 kb = Kf[(ks * 8 + j) * 32 + lane];
                uint32_t bb[2] = {kb.x, kb.y};
                mma16h(S[0][j], qf[0][ks], bb);
                mma16h(S[1][j], qf[1][ks], bb);
            }

        // ---- causal mask (last two tiles only) ----
        if (kt >= 2 * qb) {
            const int kb0 = kt * 64;
#pragma unroll
            for (int i = 0; i < 2; i++) {
                int r0 = wr + 16 * i + g;
#pragma unroll
                for (int j = 0; j < 8; j++) {
                    int c0 = kb0 + 8 * j + 2 * tg;
                    if (c0 > r0)         S[i][j][0] = -INFINITY;
                    if (c0 + 1 > r0)     S[i][j][1] = -INFINITY;
                    if (c0 > r0 + 8)     S[i][j][2] = -INFINITY;
                    if (c0 + 1 > r0 + 8) S[i][j][3] = -INFINITY;
                }
            }
        }

        // ---- online softmax in log2-scaled domain (no sum reduction) ----
#pragma unroll
        for (int i = 0; i < 2; i++) {
            float rm0 = -INFINITY, rm1 = -INFINITY;
#pragma unroll
            for (int j = 0; j < 8; j++) {
                rm0 = fmaxf(rm0, fmaxf(S[i][j][0], S[i][j][1]));
                rm1 = fmaxf(rm1, fmaxf(S[i][j][2], S[i][j][3]));
            }
            rm0 = fmaxf(rm0, __shfl_xor_sync(0xffffffffu, rm0, 1));
            rm0 = fmaxf(rm0, __shfl_xor_sync(0xffffffffu, rm0, 2));
            rm1 = fmaxf(rm1, __shfl_xor_sync(0xffffffffu, rm1, 1));
            rm1 = fmaxf(rm1, __shfl_xor_sync(0xffffffffu, rm1, 2));

            float mn0 = fmaxf(m_s[i][0], rm0 * C2F);
            float mn1 = fmaxf(m_s[i][1], rm1 * C2F);
            float a0 = ex2f(m_s[i][0] - mn0), a1 = ex2f(m_s[i][1] - mn1);
#pragma unroll
            for (int j = 0; j < 8; j++) {
                S[i][j][0] = ex2f(fmaf(S[i][j][0], C2F, -mn0));
                S[i][j][1] = ex2f(fmaf(S[i][j][1], C2F, -mn0));
                S[i][j][2] = ex2f(fmaf(S[i][j][2], C2F, -mn1));
                S[i][j][3] = ex2f(fmaf(S[i][j][3], C2F, -mn1));
            }
            m_s[i][0] = mn0;
            m_s[i][1] = mn1;
#pragma unroll
            for (int j = 0; j < 8; j++) {
                O[i][j][0] *= a0; O[i][j][1] *= a0;
                O[i][j][2] *= a1; O[i][j][3] *= a1;
            }
            Ol[i][0] *= a0; Ol[i][1] *= a0;
            Ol[i][2] *= a1; Ol[i][3] *= a1;
        }

        // ---- O += P @ V (+ ones-column for l) ----
#pragma unroll
        for (int ks = 0; ks < 4; ks++) {
            uint32_t ap[2][4];
#pragma unroll
            for (int i = 0; i < 2; i++) {
                ap[i][0] = packh2(S[i][2 * ks][0],     S[i][2 * ks][1]);
                ap[i][1] = packh2(S[i][2 * ks][2],     S[i][2 * ks][3]);
                ap[i][2] = packh2(S[i][2 * ks + 1][0], S[i][2 * ks + 1][1]);
                ap[i][3] = packh2(S[i][2 * ks + 1][2], S[i][2 * ks + 1][3]);
            }
#pragma unroll
            for (int j = 0; j < 8; j++) {
                uint2 vb = Vf[(ks * 8 + j) * 32 + lane];
                uint32_t bb[2] = {vb.x, vb.y};
                mma16h(O[0][j], ap[0], bb);
                mma16h(O[1][j], ap[1], bb);
            }
            mma16h(Ol[0], ap[0], ones_bb);
            mma16h(Ol[1], ap[1], ones_bb);
        }
    }

    // ---- epilogue: normalize (l = Ol[i][0]/[2]), pack fp16, write [B,T,E] ----
#pragma unroll
    for (int i = 0; i < 2; i++) {
        float inv0 = 1.f / Ol[i][0], inv1 = 1.f / Ol[i][2];
        int row = wr + 16 * i + g;
        uint32_t* o0 = (uint32_t*)g_attnh + ((size_t)b * T_ + row) * (E_ / 2) + h * 32;
        uint32_t* o1 = o0 + 8 * (E_ / 2);
#pragma unroll
        for (int j = 0; j < 8; j++) {
            o0[4 * j + tg] = packh2(O[i][j][0] * inv0, O[i][j][1] * inv0);
            o1[4 * j + tg] = packh2(O[i][j][2] * inv1, O[i][j][3] * inv1);
        }
    }
}

// ============================================================================
extern "C" void kernel_launch(void* const* d_in, const int* in_sizes, int n_in,
                              void* d_out, int out_size)
{
    // metadata order: k, q, v, mask, Wk, Wq, Wv, Wp, bp
    const float* k  = (const float*)d_in[0];
    const float* q  = (const float*)d_in[1];
    const float* v  = (const float*)d_in[2];
    const float* Wk = (const float*)d_in[4];
    const float* Wq = (const float*)d_in[5];
    const float* Wv = (const float*)d_in[6];
    const float* Wp = (const float*)d_in[7];
    const float* bp = (const float*)d_in[8];
    float* out = (float*)d_out;

    cudaFuncSetAttribute(proj_mma_kernel,
                         cudaFuncAttributeMaxDynamicSharedMemorySize, GEMM_SMEM_BYTES);
    cudaFuncSetAttribute(outproj_mma_kernel,
                         cudaFuncAttributeMaxDynamicSharedMemorySize, GEMM_SMEM_BYTES);
    cudaFuncSetAttribute(flash_mma_kernel,
                         cudaFuncAttributeMaxDynamicSharedMemorySize, FLASH_SMEM_BYTES);

    cvt_h_kernel<<<dim3(8192, 4), 256>>>(q, k, v, Wp);

    transpose_w_kernel<<<dim3(E_ / 64, H_, 3), 256>>>(Wq, Wk, Wv);

    proj_mma_kernel<<<dim3(T_ / 128, E_ / 128, 12), 256, GEMM_SMEM_BYTES>>>();

    flash_mma_kernel<<<dim3(T_ / 128, B_ * H_), 128, FLASH_SMEM_BYTES>>>();

    outproj_mma_kernel<<<dim3((B_ * T_) / 128, E_ / 128), 256, GEMM_SMEM_BYTES>>>(bp, out);
}

// round 10
// speedup vs baseline: 2.1592x; 1.0357x over previous
#include <cuda_runtime.h>
#include <cuda_fp16.h>
#include <math.h>
#include <stdint.h>

#define B_ 4
#define T_ 2048
#define E_ 1024
#define H_ 16

// Device-global scratch (allocation-free).
__device__ __half   g_Xh[(size_t)3 * B_ * T_ * E_];
__device__ __half   g_Wph[(size_t)E_ * E_];
__device__ __half   g_Wth[(size_t)3 * E_ * E_];
__device__ uint32_t g_Qfh[(size_t)64 * 16 * 4096];
__device__ uint32_t g_Kfh[(size_t)64 * 32 * 2048];
__device__ uint32_t g_Vfh[(size_t)64 * 32 * 2048];
__device__ __half   g_attnh[(size_t)B_ * T_ * E_];

// ============================================================================
// Helpers
// ============================================================================
__device__ __forceinline__ uint32_t packh2(float lo, float hi) {
    uint32_t r;
    asm("cvt.rn.f16x2.f32 %0, %1, %2;" : "=r"(r) : "f"(hi), "f"(lo));
    return r;
}

__device__ __forceinline__ float ex2f(float x) {
    float y;
    asm("ex2.approx.f32 %0, %1;" : "=f"(y) : "f"(x));
    return y;
}

// two fp16 exp2 in ONE MUFU op
__device__ __forceinline__ uint32_t ex2h2(uint32_t x) {
    uint32_t y;
    asm("ex2.approx.f16x2 %0, %1;" : "=r"(y) : "r"(x));
    return y;
}

__device__ __forceinline__ uint32_t smem_u32(const void* p) {
    uint32_t a;
    asm("{ .reg .u64 t; cvta.to.shared.u64 t, %1; cvt.u32.u64 %0, t; }"
        : "=r"(a) : "l"(p));
    return a;
}

// D(16x8,f32) += A(16x16,f16) * B(16x8,f16)
__device__ __forceinline__ void mma16h(float* c, const uint32_t* a, const uint32_t* b) {
    asm volatile(
        "mma.sync.aligned.m16n8k16.row.col.f32.f16.f16.f32 "
        "{%0,%1,%2,%3}, {%4,%5,%6,%7}, {%8,%9}, {%0,%1,%2,%3};"
        : "+f"(c[0]), "+f"(c[1]), "+f"(c[2]), "+f"(c[3])
        : "r"(a[0]), "r"(a[1]), "r"(a[2]), "r"(a[3]), "r"(b[0]), "r"(b[1]));
}

__device__ __forceinline__ void ldsm4(uint32_t* r, uint32_t a) {
    asm volatile("ldmatrix.sync.aligned.m8n8.x4.shared.b16 {%0,%1,%2,%3}, [%4];"
                 : "=r"(r[0]), "=r"(r[1]), "=r"(r[2]), "=r"(r[3]) : "r"(a));
}

__device__ __forceinline__ void cp16(uint32_t dst, const void* src) {
    asm volatile("cp.async.cg.shared.global [%0], [%1], 16;"
                 :: "r"(dst), "l"(src));
}
#define CP_COMMIT asm volatile("cp.async.commit_group;" ::: "memory")
#define CP_WAIT0  asm volatile("cp.async.wait_group 0;" ::: "memory")
#define CP_WAIT1  asm volatile("cp.async.wait_group 1;" ::: "memory")

// ============================================================================
// Convert pass: g_Xh[z] = fp16(q|k|v), g_Wph = fp16(Wp)
// ============================================================================
__global__ __launch_bounds__(256) void cvt_h_kernel(
    const float* __restrict__ q, const float* __restrict__ k,
    const float* __restrict__ v, const float* __restrict__ Wp)
{
    const int z = blockIdx.y;
    const float* src;
    __half* dst;
    size_t n4;
    if (z < 3) {
        src = (z == 0 ? q : (z == 1 ? k : v));
        dst = g_Xh + (size_t)z * B_ * T_ * E_;
        n4  = (size_t)B_ * T_ * E_ / 4;
    } else {
        src = Wp;
        dst = g_Wph;
        n4  = (size_t)E_ * E_ / 4;
    }
    size_t i = (size_t)blockIdx.x * 256 + threadIdx.x;
    if (i < n4) {
        float4 x = ((const float4*)src)[i];
        uint2 o;
        o.x = packh2(x.x, x.y);
        o.y = packh2(x.z, x.w);
        ((uint2*)dst)[i] = o;
    }
}

// ============================================================================
// Weight transpose: g_Wth[which][h*64+d][e] = fp16(W[which][h][e][d])
// ============================================================================
__global__ __launch_bounds__(256) void transpose_w_kernel(
    const float* __restrict__ Wq, const float* __restrict__ Wk,
    const float* __restrict__ Wv)
{
    __shared__ float tile[64][65];
    const int which = blockIdx.z;
    const int h     = blockIdx.y;
    const int e0    = blockIdx.x * 64;
    const float* W = (which == 0 ? Wq : (which == 1 ? Wk : Wv)) + (size_t)h * E_ * 64;
    const int tid = threadIdx.x;

#pragma unroll
    for (int u = 0; u < 16; u++) {
        int idx = tid + u * 256;
        int r = idx >> 6, c = idx & 63;
        tile[r][c] = W[(size_t)(e0 + r) * 64 + c];
    }
    __syncthreads();

    __half* out = g_Wth + (size_t)which * E_ * E_;
#pragma unroll
    for (int u = 0; u < 16; u++) {
        int idx = tid + u * 256;
        int d = idx >> 6, ee = idx & 63;
        out[(size_t)(h * 64 + d) * E_ + e0 + ee] = __float2half_rn(tile[ee][d]);
    }
}

// ============================================================================
// fp16 GEMM core (cp.async 3-stage, ldmatrix, BK=64):
// C[128,128] = A[128,K=1024] @ B[128,K=1024]^T, 16 chunks of 64 (4 k16 steps).
// 256 threads / 8 warps (4M x 2N), warp tile 32x64. smem row 72 halves.
// ============================================================================
#define HLD 36
#define GSW (128 * HLD)
#define GEMM_SMEM_BYTES (6 * GSW * 4)        // 110592

__device__ __forceinline__ void gemm_issue_h(
    const __half* __restrict__ A, const __half* __restrict__ Bm,
    uint32_t su, int c, int s, int tid)
{
    const __half* Ac = A + (c << 6);
    const __half* Bc = Bm + (c << 6);
    const uint32_t ab = su + (uint32_t)s * GSW * 4;
    const uint32_t bb = su + (uint32_t)(3 + s) * GSW * 4;
#pragma unroll
    for (int u = 0; u < 4; u++) {
        int idx = tid + (u << 8);           // 0..1023
        int r = idx >> 3, qq = idx & 7;
        uint32_t so = (uint32_t)r * 144 + (uint32_t)qq * 16;
        cp16(ab + so, Ac + (size_t)r * E_ + (qq << 3));
        cp16(bb + so, Bc + (size_t)r * E_ + (qq << 3));
    }
    CP_COMMIT;
}

__device__ __forceinline__ void gemm_tile_h(
    const __half* __restrict__ A, const __half* __restrict__ Bm,
    uint32_t* smw, float C[2][8][4])
{
    const int tid = threadIdx.x, wid = tid >> 5, lane = tid & 31;
    const int mw = (wid & 3) * 32, nw = (wid >> 2) * 64;
    const int i0 = lane & 7, sel = lane >> 3;
    const uint32_t su = smem_u32(smw);

    const int arow = (mw + i0 + ((sel & 1) << 3)) * HLD + ((sel >> 1) << 2);
    int brow[4];
#pragma unroll
    for (int p = 0; p < 4; p++)
        brow[p] = (nw + 16 * p + ((sel >> 1) << 3) + i0) * HLD + ((sel & 1) << 2);

#pragma unroll
    for (int i = 0; i < 2; i++)
#pragma unroll
        for (int j = 0; j < 8; j++)
#pragma unroll
            for (int p = 0; p < 4; p++) C[i][j][p] = 0.f;

    gemm_issue_h(A, Bm, su, 0, 0, tid);
    gemm_issue_h(A, Bm, su, 1, 1, tid);

    int s = 0;
    for (int c = 0; c < 16; c++) {
        if (c < 15) { CP_WAIT1; } else { CP_WAIT0; }
        __syncthreads();
        if (c + 2 < 16) {
            int sn = s + 2; if (sn >= 3) sn -= 3;
            gemm_issue_h(A, Bm, su, c + 2, sn, tid);
        }
        const uint32_t aBase = su + (uint32_t)s * (GSW * 4);
        const uint32_t bBase = su + (uint32_t)(3 + s) * (GSW * 4);
#pragma unroll
        for (int ks = 0; ks < 4; ks++) {
            const int ko = ks * 8;
            uint32_t af[2][4], bf[4][4];
            ldsm4(af[0], aBase + (uint32_t)(arow + ko) * 4);
            ldsm4(af[1], aBase + (uint32_t)(arow + 16 * HLD + ko) * 4);
#pragma unroll
            for (int p = 0; p < 4; p++)
                ldsm4(bf[p], bBase + (uint32_t)(brow[p] + ko) * 4);
#pragma unroll
            for (int i = 0; i < 2; i++)
#pragma unroll
                for (int p = 0; p < 4; p++) {
                    mma16h(C[i][2 * p],     af[i], &bf[p][0]);
                    mma16h(C[i][2 * p + 1], af[i], &bf[p][2]);
                }
        }
        if (++s == 3) s = 0;
    }
}

// ============================================================================
// QKV projection: grid (T/128, E/128, 12 = which*4+b).
// Epilogue packs fp16x2 and scatters into fragment blobs. Q stays UNscaled.
// ============================================================================
__global__ __launch_bounds__(256, 2) void proj_mma_kernel()
{
    extern __shared__ uint32_t gsm[];
    const int which = blockIdx.z >> 2;
    const int b     = blockIdx.z & 3;
    const int t0    = blockIdx.x * 128;
    const int n0    = blockIdx.y * 128;
    const __half* X  = g_Xh + ((size_t)which * B_ + b) * T_ * E_ + (size_t)t0 * E_;
    const __half* Bm = g_Wth + (size_t)which * E_ * E_ + (size_t)n0 * E_;

    float C[2][8][4];
    gemm_tile_h(X, Bm, gsm, C);

    const int lane = threadIdx.x & 31, wid = threadIdx.x >> 5;
    const int ge = lane >> 2, te = lane & 3;
    const int mw = (wid & 3) * 32, nw = (wid >> 2) * 64;

#pragma unroll
    for (int i = 0; i < 2; i++) {
        const int t_lo = t0 + mw + 16 * i + ge;
#pragma unroll
        for (int j = 0; j < 8; j++) {
            const int c  = n0 + nw + 8 * j + 2 * te;
            const int h  = c >> 6, d = c & 63;
            const int bh = b * 16 + h;

            if (which == 0) {
                uint32_t w01 = packh2(C[i][j][0], C[i][j][1]);
                uint32_t w23 = packh2(C[i][j][2], C[i][j][3]);
                int qb = t_lo >> 7, tl = t_lo & 127;
                int rb = tl >> 4, gp = tl & 7;
                int ks = d >> 4, dk = d & 15;
                int tgp = (dk >> 1) & 3, rhi = (dk >> 3) << 1;
                size_t idx = ((size_t)bh * 16 + qb) * 4096 +
                             (size_t)(((ks * 8 + rb) * 32 + 4 * gp + tgp) * 4 + rhi);
                uint2 st; st.x = w01; st.y = w23;
                *(uint2*)&g_Qfh[idx] = st;
            } else if (which == 1) {
                uint32_t w01 = packh2(C[i][j][0], C[i][j][1]);
                uint32_t w23 = packh2(C[i][j][2], C[i][j][3]);
                int kt = t_lo >> 6, sidx = t_lo & 63;
                int jp = sidx >> 3, gp = sidx & 7;
                int ks = d >> 4, dk = d & 15;
                int reg = dk >> 3, tgp = (dk >> 1) & 3;
                size_t base = ((size_t)bh * 32 + kt) * 2048;
                g_Kfh[base + ((ks * 8 + jp) * 32 + 4 * gp + tgp) * 2 + reg] = w01;
                g_Kfh[base + ((ks * 8 + jp + 1) * 32 + 4 * gp + tgp) * 2 + reg] = w23;
            } else {
                float q0 = __shfl_xor_sync(0xffffffffu, C[i][j][0], 4);
                float q1 = __shfl_xor_sync(0xffffffffu, C[i][j][1], 4);
                float q2 = __shfl_xor_sync(0xffffffffu, C[i][j][2], 4);
                float q3 = __shfl_xor_sync(0xffffffffu, C[i][j][3], 4);
                if ((ge & 1) == 0) {
                    uint32_t wA = packh2(C[i][j][0], q0);
                    uint32_t wB = packh2(C[i][j][1], q1);
                    uint32_t wC = packh2(C[i][j][2], q2);
                    uint32_t wD = packh2(C[i][j][3], q3);
                    int kt = t_lo >> 6, sidx = t_lo & 63;
                    int ks = sidx >> 4, sk = sidx & 15;
                    int tgp = (sk >> 1) & 3;
                    int jp = d >> 3, gp = d & 7;
                    size_t base = ((size_t)bh * 32 + kt) * 2048;
                    size_t iA = base + ((ks * 8 + jp) * 32 + 4 * gp + tgp) * 2;
                    size_t iB = base + ((ks * 8 + jp) * 32 + 4 * (gp + 1) + tgp) * 2;
                    uint2 s0; s0.x = wA; s0.y = wC;
                    uint2 s1; s1.x = wB; s1.y = wD;
                    *(uint2*)&g_Vfh[iA] = s0;
                    *(uint2*)&g_Vfh[iB] = s1;
                }
            }
        }
    }
}

// ============================================================================
// Output projection: out = attn(fp16) @ Wp(fp16)^T + bp (fp32 epilogue).
// ============================================================================
__global__ __launch_bounds__(256, 2) void outproj_mma_kernel(
    const float* __restrict__ bp, float* __restrict__ out)
{
    extern __shared__ uint32_t gsm[];
    const int m0 = blockIdx.x * 128;
    const int n0 = blockIdx.y * 128;

    float C[2][8][4];
    gemm_tile_h(g_attnh + (size_t)m0 * E_, g_Wph + (size_t)n0 * E_, gsm, C);

    const int lane = threadIdx.x & 31, wid = threadIdx.x >> 5;
    const int g = lane >> 2, tg = lane & 3;
    const int mw = (wid & 3) * 32, nw = (wid >> 2) * 64;

#pragma unroll
    for (int i = 0; i < 2; i++) {
        size_t r = (size_t)(m0 + mw + 16 * i + g);
#pragma unroll
        for (int j = 0; j < 8; j++) {
            int cc = n0 + nw + 8 * j + 2 * tg;
            float2 bv = *(const float2*)&bp[cc];
            float2 v0 = {C[i][j][0] + bv.x, C[i][j][1] + bv.y};
            float2 v1 = {C[i][j][2] + bv.x, C[i][j][3] + bv.y};
            *(float2*)&out[r * E_ + cc] = v0;
            *(float2*)&out[(r + 8) * E_ + cc] = v1;
        }
    }
}

// ============================================================================
// Causal flash attention, fp16 m16n8k16, log2-domain online softmax with
// f16x2 MUFU exp (2 exps per MUFU op; PV A-frags come straight out of ex2).
// 128-row CTA, 4 warps x 32 rows. Q blob once; K,V triple-buffered,
// ONE __syncthreads per iteration. l via ones-column MMA.
// grid (T/128, B*H), 128 threads.
// ============================================================================
#define FQW 4096
#define FKW 2048
#define FLASH_SMEM_BYTES ((FQW + 3 * FKW + 3 * FKW) * 4)   // 65536
#define C2F 0.0450844331f   // log2(e) / 32
#define ONESH2 0x3C003C00u  // fp16x2 {1,1}

__global__ __launch_bounds__(128, 2) void flash_mma_kernel()
{
    extern __shared__ uint32_t smf[];
    uint32_t* Qs  = smf;
    uint32_t* Ks3 = smf + FQW;
    uint32_t* Vs3 = smf + FQW + 3 * FKW;

    const int bh = blockIdx.y;
    const int b  = bh >> 4, h = bh & 15;
    const int qb = gridDim.x - 1 - blockIdx.x;
    const int tid = threadIdx.x, w = tid >> 5, lane = tid & 31;
    const int g = lane >> 2, tg = lane & 3;
    const int last = 2 * qb + 1;

    const uint32_t* Qg = g_Qfh + ((size_t)bh * 16 + qb) * FQW;
    const uint32_t* Kg = g_Kfh + (size_t)bh * 32 * FKW;
    const uint32_t* Vg = g_Vfh + (size_t)bh * 32 * FKW;

    const uint32_t qs_u = smem_u32(Qs);
    const uint32_t ks_u = smem_u32(Ks3);
    const uint32_t vs_u = smem_u32(Vs3);

    auto issueKV = [&](int kt) {
        int st = kt % 3;
        const uint32_t kb = ks_u + (uint32_t)(st * FKW * 4);
        const uint32_t vb = vs_u + (uint32_t)(st * FKW * 4);
        const uint32_t* Kp = Kg + (size_t)kt * FKW;
        const uint32_t* Vp = Vg + (size_t)kt * FKW;
#pragma unroll
        for (int u = 0; u < 4; u++) {
            int idx = tid + (u << 7);
            cp16(kb + (uint32_t)idx * 16, Kp + (size_t)idx * 4);
            cp16(vb + (uint32_t)idx * 16, Vp + (size_t)idx * 4);
        }
        CP_COMMIT;
    };

    {
#pragma unroll
        for (int u = 0; u < 8; u++) {
            int idx = tid + (u << 7);
            cp16(qs_u + (uint32_t)idx * 16, Qg + (size_t)idx * 4);
        }
#pragma unroll
        for (int u = 0; u < 4; u++) {
            int idx = tid + (u << 7);
            cp16(ks_u + (uint32_t)idx * 16, Kg + (size_t)idx * 4);
            cp16(vs_u + (uint32_t)idx * 16, Vg + (size_t)idx * 4);
        }
        CP_COMMIT;
        if (last >= 1) issueKV(1);
    }

    uint32_t qf[2][4][4];
    float O[2][8][4];
    float Ol[2][4];                 // ones-column accumulators (l in [0],[2])
    float m_s[2][2];
#pragma unroll
    for (int i = 0; i < 2; i++) {
        m_s[i][0] = -INFINITY; m_s[i][1] = -INFINITY;
#pragma unroll
        for (int p = 0; p < 4; p++) Ol[i][p] = 0.f;
#pragma unroll
        for (int j = 0; j < 8; j++)
#pragma unroll
            for (int p = 0; p < 4; p++) O[i][j][p] = 0.f;
    }

    const int wr = qb * 128 + 32 * w;
    const uint32_t ones_bb[2] = {ONESH2, ONESH2};

    for (int kt = 0; kt <= last; kt++) {
        if (kt < last) { CP_WAIT1; } else { CP_WAIT0; }
        __syncthreads();
        if (kt + 2 <= last) issueKV(kt + 2);

        if (kt == 0) {
            const uint4* Qf4 = (const uint4*)Qs;
#pragma unroll
            for (int ks = 0; ks < 4; ks++)
#pragma unroll
                for (int i = 0; i < 2; i++) {
                    uint4 qa = Qf4[(ks * 8 + 2 * w + i) * 32 + lane];
                    qf[i][ks][0] = qa.x; qf[i][ks][1] = qa.y;
                    qf[i][ks][2] = qa.z; qf[i][ks][3] = qa.w;
                }
        }

        const int st = kt % 3;
        const uint2* Kf = (const uint2*)(Ks3 + (size_t)st * FKW);
        const uint2* Vf = (const uint2*)(Vs3 + (size_t)st * FKW);

        // ---- S = Q @ K^T (raw, unscaled) ----
        float S[2][8][4];
#pragma unroll
        for (int i = 0; i < 2; i++)
#pragma unroll
            for (int j = 0; j < 8; j++)
#pragma unroll
                for (int p = 0; p < 4; p++) S[i][j][p] = 0.f;

#pragma unroll
        for (int ks = 0; ks < 4; ks++)
#pragma unroll
            for (int j = 0; j < 8; j++) {
                uint2 kb = Kf[(ks * 8 + j) * 32 + lane];
                uint32_t bb[2] = {kb.x, kb.y};
                mma16h(S[0][j], qf[0][ks], bb);
                mma16h(S[1][j], qf[1][ks], bb);
            }

        // ---- causal mask (last two tiles only) ----
        if (kt >= 2 * qb) {
            const int kb0 = kt * 64;
#pragma unroll
            for (int i = 0; i < 2; i++) {
                int r0 = wr + 16 * i + g;
#pragma unroll
                for (int j = 0; j < 8; j++) {
                    int c0 = kb0 + 8 * j + 2 * tg;
                    if (c0 > r0)         S[i][j][0] = -INFINITY;
                    if (c0 + 1 > r0)     S[i][j][1] = -INFINITY;
                    if (c0 > r0 + 8)     S[i][j][2] = -INFINITY;
                    if (c0 + 1 > r0 + 8) S[i][j][3] = -INFINITY;
                }
            }
        }

        // ---- online softmax: exp via f16x2 MUFU, P lands as fp16x2 A-frags ----
        uint32_t Ph[2][8][2];
#pragma unroll
        for (int i = 0; i < 2; i++) {
            float rm0 = -INFINITY, rm1 = -INFINITY;
#pragma unroll
            for (int j = 0; j < 8; j++) {
                rm0 = fmaxf(rm0, fmaxf(S[i][j][0], S[i][j][1]));
                rm1 = fmaxf(rm1, fmaxf(S[i][j][2], S[i][j][3]));
            }
            rm0 = fmaxf(rm0, __shfl_xor_sync(0xffffffffu, rm0, 1));
            rm0 = fmaxf(rm0, __shfl_xor_sync(0xffffffffu, rm0, 2));
            rm1 = fmaxf(rm1, __shfl_xor_sync(0xffffffffu, rm1, 1));
            rm1 = fmaxf(rm1, __shfl_xor_sync(0xffffffffu, rm1, 2));

            float mn0 = fmaxf(m_s[i][0], rm0 * C2F);
            float mn1 = fmaxf(m_s[i][1], rm1 * C2F);
            float a0 = ex2f(m_s[i][0] - mn0), a1 = ex2f(m_s[i][1] - mn1);
#pragma unroll
            for (int j = 0; j < 8; j++) {
                float e0 = fmaf(S[i][j][0], C2F, -mn0);
                float e1 = fmaf(S[i][j][1], C2F, -mn0);
                float e2 = fmaf(S[i][j][2], C2F, -mn1);
                float e3 = fmaf(S[i][j][3], C2F, -mn1);
                Ph[i][j][0] = ex2h2(packh2(e0, e1));   // rows g   : P, fp16x2
                Ph[i][j][1] = ex2h2(packh2(e2, e3));   // rows g+8 : P, fp16x2
            }
            m_s[i][0] = mn0;
            m_s[i][1] = mn1;
#pragma unroll
            for (int j = 0; j < 8; j++) {
                O[i][j][0] *= a0; O[i][j][1] *= a0;
                O[i][j][2] *= a1; O[i][j][3] *= a1;
            }
            Ol[i][0] *= a0;
            Ol[i][2] *= a1;
        }

        // ---- O += P @ V (+ ones-column for l); A-frags = Ph directly ----
#pragma unroll
        for (int ks = 0; ks < 4; ks++) {
            uint32_t ap[2][4];
#pragma unroll
            for (int i = 0; i < 2; i++) {
                ap[i][0] = Ph[i][2 * ks][0];
                ap[i][1] = Ph[i][2 * ks][1];
                ap[i][2] = Ph[i][2 * ks + 1][0];
                ap[i][3] = Ph[i][2 * ks + 1][1];
            }
#pragma unroll
            for (int j = 0; j < 8; j++) {
                uint2 vb = Vf[(ks * 8 + j) * 32 + lane];
                uint32_t bb[2] = {vb.x, vb.y};
                mma16h(O[0][j], ap[0], bb);
                mma16h(O[1][j], ap[1], bb);
            }
            mma16h(Ol[0], ap[0], ones_bb);
            mma16h(Ol[1], ap[1], ones_bb);
        }
    }

    // ---- epilogue: normalize (l = Ol[i][0]/[2]), pack fp16, write [B,T,E] ----
#pragma unroll
    for (int i = 0; i < 2; i++) {
        float inv0 = 1.f / Ol[i][0], inv1 = 1.f / Ol[i][2];
        int row = wr + 16 * i + g;
        uint32_t* o0 = (uint32_t*)g_attnh + ((size_t)b * T_ + row) * (E_ / 2) + h * 32;
        uint32_t* o1 = o0 + 8 * (E_ / 2);
#pragma unroll
        for (int j = 0; j < 8; j++) {
            o0[4 * j + tg] = packh2(O[i][j][0] * inv0, O[i][j][1] * inv0);
            o1[4 * j + tg] = packh2(O[i][j][2] * inv1, O[i][j][3] * inv1);
        }
    }
}

// ============================================================================
extern "C" void kernel_launch(void* const* d_in, const int* in_sizes, int n_in,
                              void* d_out, int out_size)
{
    // metadata order: k, q, v, mask, Wk, Wq, Wv, Wp, bp
    const float* k  = (const float*)d_in[0];
    const float* q  = (const float*)d_in[1];
    const float* v  = (const float*)d_in[2];
    const float* Wk = (const float*)d_in[4];
    const float* Wq = (const float*)d_in[5];
    const float* Wv = (const float*)d_in[6];
    const float* Wp = (const float*)d_in[7];
    const float* bp = (const float*)d_in[8];
    float* out = (float*)d_out;

    cudaFuncSetAttribute(proj_mma_kernel,
                         cudaFuncAttributeMaxDynamicSharedMemorySize, GEMM_SMEM_BYTES);
    cudaFuncSetAttribute(outproj_mma_kernel,
                         cudaFuncAttributeMaxDynamicSharedMemorySize, GEMM_SMEM_BYTES);
    cudaFuncSetAttribute(flash_mma_kernel,
                         cudaFuncAttributeMaxDynamicSharedMemorySize, FLASH_SMEM_BYTES);

    cvt_h_kernel<<<dim3(8192, 4), 256>>>(q, k, v, Wp);

    transpose_w_kernel<<<dim3(E_ / 64, H_, 3), 256>>>(Wq, Wk, Wv);

    proj_mma_kernel<<<dim3(T_ / 128, E_ / 128, 12), 256, GEMM_SMEM_BYTES>>>();

    flash_mma_kernel<<<dim3(T_ / 128, B_ * H_), 128, FLASH_SMEM_BYTES>>>();

    outproj_mma_kernel<<<dim3((B_ * T_) / 128, E_ / 128), 256, GEMM_SMEM_BYTES>>>(bp, out);
}